// round 13
// baseline (speedup 1.0000x reference)
#include <cuda_runtime.h>
#include <cuda_fp16.h>
#include <math.h>
#include <stdint.h>

#define T_ 4096
#define I_ 2048
#define HD 2048
#define K_ 3
#define NCOL 18432            // 3*3H
#define WS_ (HD + I_)
#define THETA 4e-3f           // ambiguity threshold on top-2 logit gap (~9.3 sigma)
#define MAXF 128              // max flagged steps (expected ~16)

// ---------------- scratch (device globals) ---------------------------------
__device__ float g_gi[(size_t)T_ * NCOL];        // 1-product GEMM out ~302MB
__device__ float g_Hall[(size_t)T_ * K_ * HD];   // ~100.7MB
__device__ __half g_xhi[(size_t)T_ * I_];
__device__ __half g_whi[(size_t)NCOL * I_];
__device__ float g_D[(size_t)T_ * K_ * K_];
__device__ float g_selx[(size_t)T_ * K_];
__device__ float g_dfix[(size_t)MAXF * NCOL];    // exact corrections for flagged rows
__device__ int g_fixn;
__device__ int g_fixlist[MAXF];
__device__ unsigned int g_fw[T_];
__device__ int g_kk[T_];

// ---------------- helpers ---------------------------------------------------
__device__ __forceinline__ uint32_t smem_u32(const void* p) {
    uint32_t a;
    asm("{ .reg .u64 t; cvta.to.shared.u64 t, %1; cvt.u32.u64 %0, t; }" : "=r"(a) : "l"(p));
    return a;
}
__device__ __forceinline__ void cp16(uint32_t s, const void* g) {
    asm volatile("cp.async.cg.shared.global [%0], [%1], 16;" :: "r"(s), "l"(g));
}
#define CP_COMMIT() asm volatile("cp.async.commit_group;" ::: "memory")
#define CP_WAIT0()  asm volatile("cp.async.wait_group 0;" ::: "memory")
#define CP_WAIT1()  asm volatile("cp.async.wait_group 1;" ::: "memory")

__device__ __forceinline__ void ldsm_x4(uint32_t& r0, uint32_t& r1, uint32_t& r2,
                                        uint32_t& r3, uint32_t a) {
    asm volatile("ldmatrix.sync.aligned.m8n8.x4.shared.b16 {%0,%1,%2,%3}, [%4];"
                 : "=r"(r0), "=r"(r1), "=r"(r2), "=r"(r3) : "r"(a));
}
__device__ __forceinline__ void mma16816(float* d, const uint32_t* a, uint32_t b0, uint32_t b1) {
    asm volatile("mma.sync.aligned.m16n8k16.row.col.f32.f16.f16.f32 "
                 "{%0,%1,%2,%3}, {%4,%5,%6,%7}, {%8,%9}, {%0,%1,%2,%3};"
                 : "+f"(d[0]), "+f"(d[1]), "+f"(d[2]), "+f"(d[3])
                 : "r"(a[0]), "r"(a[1]), "r"(a[2]), "r"(a[3]), "r"(b0), "r"(b1));
}

// fast, saturation-safe sigmoid / tanh (abs err ~1e-7, << 4e-4 budget)
__device__ __forceinline__ float fsig(float x)  { return 1.0f / (1.0f + __expf(-x)); }
__device__ __forceinline__ float ftanh(float x) { return 2.0f / (1.0f + __expf(-2.0f * x)) - 1.0f; }

// ---------------------------------------------------------------------------
// K0: fp32 -> fp16 (round-to-nearest) conversion
// ---------------------------------------------------------------------------
__global__ __launch_bounds__(256) void k0_half(
    const float* __restrict__ src, __half* __restrict__ hi, size_t n4)
{
    size_t i = (size_t)blockIdx.x * 256 + threadIdx.x;
    if (i >= n4) return;
    float4 v = *(const float4*)(src + i * 4);
    __half h[4];
    h[0] = __float2half_rn(v.x); h[1] = __float2half_rn(v.y);
    h[2] = __float2half_rn(v.z); h[3] = __float2half_rn(v.w);
    *(uint2*)(hi + i * 4) = *(uint2*)h;
}

// ---------------------------------------------------------------------------
// K1: gi = xhi @ whi^T  -- single fp16 HMMA product.
// CTA 128x128; 3-stage cp.async ring with FETCH DISTANCE 2 (wait_group 1):
//   stage s: wait<=1 (s landed; s+1 may fly) -> sync -> fetch(s+2) -> compute.
// Copies get a ~2-stage latency window, killing stage-boundary copy stalls.
// 61.4KB smem/CTA -> 2 CTAs/SM.
// ---------------------------------------------------------------------------
#define BK 32
#define ROWB 80
#define TILEB (128 * ROWB)        // 10240
#define STAGEB (2 * TILEB)        // 20480 (A_hi, B_hi)
#define NSTG 3
#define K1_SMEM (NSTG * STAGEB)   // 61440
#define NS (I_ / BK)              // 64

__global__ void __launch_bounds__(256, 2) k1_mma(
    const __half* __restrict__ xhi, const __half* __restrict__ whi)
{
    extern __shared__ char smem[];
    const uint32_t sbase = smem_u32(smem);
    const int tid = threadIdx.x;
    const int wid = tid >> 5;
    const int lane = tid & 31;

    const int t0 = blockIdx.x * 128;   // M
    const int c0 = blockIdx.y * 128;   // N

    const int warpM = (wid & 3) * 32;
    const int warpN = (wid >> 2) * 64;

    float acc[2][8][4];
#pragma unroll
    for (int i = 0; i < 2; i++)
#pragma unroll
        for (int j = 0; j < 8; j++)
#pragma unroll
            for (int q = 0; q < 4; q++) acc[i][j][q] = 0.f;

    auto fetch = [&](int s) {
        const int stg = s % NSTG;
        const uint32_t bA_hi = sbase + stg * STAGEB;
        const uint32_t bB_hi = bA_hi + TILEB;
        const int k0 = s * BK;
#pragma unroll
        for (int it = 0; it < 2; it++) {
            int c = it * 256 + tid;
            int kc = c >> 7;
            int row = c & 127;
            uint32_t so = (uint32_t)(row * ROWB + kc * 16);
            size_t ga = (size_t)(t0 + row) * I_ + k0 + kc * 8;
            size_t gb = (size_t)(c0 + row) * I_ + k0 + kc * 8;
            cp16(bA_hi + so, xhi + ga);
            cp16(bB_hi + so, whi + gb);
        }
    };

    fetch(0); CP_COMMIT();
    fetch(1); CP_COMMIT();

    for (int s = 0; s < NS; s++) {
        if (s + 1 < NS) CP_WAIT1();   // stage s landed (s+1 may be in flight)
        else            CP_WAIT0();   // final stage: only group s pending
        __syncthreads();              // publish s; all warps done with (s+2)%3

        if (s + 2 < NS) { fetch(s + 2); CP_COMMIT(); }

        const int stg = s % NSTG;
        const uint32_t bA_hi = sbase + stg * STAGEB;
        const uint32_t bB_hi = bA_hi + TILEB;

#pragma unroll
        for (int kc = 0; kc < 2; kc++) {
            const uint32_t kb = kc * 32 + (lane >> 4) * 16;
            const uint32_t rsel = (lane & 15);

            uint32_t Ah[2][4];
#pragma unroll
            for (int i = 0; i < 2; i++) {
                uint32_t off = (uint32_t)((warpM + i * 16 + rsel) * ROWB) + kb;
                ldsm_x4(Ah[i][0], Ah[i][1], Ah[i][2], Ah[i][3], bA_hi + off);
            }
#pragma unroll
            for (int g = 0; g < 4; g++) {
                uint32_t Bhg[4];
                uint32_t off = (uint32_t)((warpN + g * 16 + rsel) * ROWB) + kb;
                ldsm_x4(Bhg[0], Bhg[1], Bhg[2], Bhg[3], bB_hi + off);
#pragma unroll
                for (int i = 0; i < 2; i++) {
#pragma unroll
                    for (int sel = 0; sel < 2; sel++) {
                        const int j = g * 2 + sel;
                        mma16816(acc[i][j], Ah[i], Bhg[sel], Bhg[sel + 2]);
                    }
                }
            }
        }
    }

#pragma unroll
    for (int i = 0; i < 2; i++) {
#pragma unroll
        for (int j = 0; j < 8; j++) {
            int row = t0 + warpM + i * 16 + (lane >> 2);
            int col = c0 + warpN + j * 8 + (lane & 3) * 2;
            float2 u0 = make_float2(acc[i][j][0], acc[i][j][1]);
            float2 u1 = make_float2(acc[i][j][2], acc[i][j][3]);
            *(float2*)&g_gi[(size_t)row * NCOL + col] = u0;
            *(float2*)&g_gi[(size_t)(row + 8) * NCOL + col] = u1;
        }
    }
}

// ---------------------------------------------------------------------------
// gates: Hall[t][k][o]  (fast-intrinsic gate math; DRAM-bound now)
// ---------------------------------------------------------------------------
__global__ __launch_bounds__(256) void k_gates(
    const float* __restrict__ bih, const float* __restrict__ bhh)
{
    size_t idx = (size_t)blockIdx.x * 256 + threadIdx.x;
    int o4 = (int)(idx % (HD / 4));
    int k  = (int)((idx / (HD / 4)) % K_);
    int t  = (int)(idx / ((size_t)K_ * (HD / 4)));

    const float* base = g_gi + (size_t)t * NCOL + (size_t)k * 3 * HD + o4 * 4;
    float4 ir4 = *(const float4*)(base);
    float4 iz4 = *(const float4*)(base + HD);
    float4 in4 = *(const float4*)(base + 2 * HD);

    const float* bi = bih + (size_t)k * 3 * HD;
    const float* bh = bhh + (size_t)k * 3 * HD;
    float4 br = *(const float4*)(bi + o4 * 4);
    float4 bz = *(const float4*)(bi + HD + o4 * 4);
    float4 bn = *(const float4*)(bi + 2 * HD + o4 * 4);
    float4 hr = *(const float4*)(bh + o4 * 4);
    float4 hz = *(const float4*)(bh + HD + o4 * 4);
    float4 hn = *(const float4*)(bh + 2 * HD + o4 * 4);

    float irs[4] = {ir4.x, ir4.y, ir4.z, ir4.w};
    float izs[4] = {iz4.x, iz4.y, iz4.z, iz4.w};
    float ins[4] = {in4.x, in4.y, in4.z, in4.w};
    float brs[4] = {br.x, br.y, br.z, br.w};
    float bzs[4] = {bz.x, bz.y, bz.z, bz.w};
    float bns[4] = {bn.x, bn.y, bn.z, bn.w};
    float hrs[4] = {hr.x, hr.y, hr.z, hr.w};
    float hzs[4] = {hz.x, hz.y, hz.z, hz.w};
    float hns[4] = {hn.x, hn.y, hn.z, hn.w};

    float res[4];
#pragma unroll
    for (int n = 0; n < 4; n++) {
        float r = fsig(irs[n] + brs[n] + hrs[n]);
        float z = fsig(izs[n] + bzs[n] + hzs[n]);
        float nn = ftanh(ins[n] + bns[n] + r * hns[n]);
        res[n] = (1.0f - z) * nn;
    }
    float4 o;
    o.x = res[0]; o.y = res[1]; o.z = res[2]; o.w = res[3];
    *(float4*)&g_Hall[((size_t)t * K_ + k) * HD + o4 * 4] = o;
}

// ---------------------------------------------------------------------------
// K2: D + sel_x
// ---------------------------------------------------------------------------
__global__ __launch_bounds__(256) void k2_Dselx(
    const float* __restrict__ xs, const float* __restrict__ Wsel,
    const float* __restrict__ bsel)
{
    const int t = blockIdx.x;
    float aD[9] = {0.f, 0.f, 0.f, 0.f, 0.f, 0.f, 0.f, 0.f, 0.f};
    float aS[3] = {0.f, 0.f, 0.f};

    const float* hrow = g_Hall + (size_t)t * K_ * HD;
    const float* xrow = xs + (size_t)t * I_;

    for (int h = threadIdx.x; h < HD; h += 256) {
        float w0 = Wsel[0 * WS_ + h];
        float w1 = Wsel[1 * WS_ + h];
        float w2 = Wsel[2 * WS_ + h];
#pragma unroll
        for (int j = 0; j < 3; j++) {
            float hv = hrow[(size_t)j * HD + h];
            aD[j * 3 + 0] = fmaf(hv, w0, aD[j * 3 + 0]);
            aD[j * 3 + 1] = fmaf(hv, w1, aD[j * 3 + 1]);
            aD[j * 3 + 2] = fmaf(hv, w2, aD[j * 3 + 2]);
        }
    }
    for (int i = threadIdx.x; i < I_; i += 256) {
        float xv = xrow[i];
        aS[0] = fmaf(xv, Wsel[0 * WS_ + HD + i], aS[0]);
        aS[1] = fmaf(xv, Wsel[1 * WS_ + HD + i], aS[1]);
        aS[2] = fmaf(xv, Wsel[2 * WS_ + HD + i], aS[2]);
    }

    float vals[12];
#pragma unroll
    for (int v = 0; v < 9; v++) vals[v] = aD[v];
#pragma unroll
    for (int v = 0; v < 3; v++) vals[9 + v] = aS[v];

    __shared__ float red[12][8];
    int lane = threadIdx.x & 31, w = threadIdx.x >> 5;
#pragma unroll
    for (int v = 0; v < 12; v++) {
        float s = vals[v];
        for (int off = 16; off > 0; off >>= 1)
            s += __shfl_down_sync(0xffffffffu, s, off);
        if (lane == 0) red[v][w] = s;
    }
    __syncthreads();
    if (threadIdx.x < 12) {
        float s = 0.f;
#pragma unroll
        for (int ww = 0; ww < 8; ww++) s += red[threadIdx.x][ww];
        if (threadIdx.x < 9)
            g_D[(size_t)t * 9 + threadIdx.x] = s;
        else
            g_selx[(size_t)t * 3 + (threadIdx.x - 9)] = s + bsel[threadIdx.x - 9];
    }
}

// ---------------------------------------------------------------------------
// reset fix counter (graph replays!)
// ---------------------------------------------------------------------------
__global__ void k_zero() { g_fixn = 0; }

// ---------------------------------------------------------------------------
// K3a: flag ambiguous steps (any j-row with top-2 gap < THETA) -> fixlist
// ---------------------------------------------------------------------------
__global__ void k3_flag()
{
    int t = blockIdx.x * blockDim.x + threadIdx.x;
    if (t < 1 || t >= T_) return;
    const float* d = g_D + (size_t)(t - 1) * 9;
    float s0 = g_selx[t * 3 + 0];
    float s1 = g_selx[t * 3 + 1];
    float s2 = g_selx[t * 3 + 2];
    bool amb = false;
#pragma unroll
    for (int j = 0; j < 3; j++) {
        float l0 = d[j * 3 + 0] + s0;
        float l1 = d[j * 3 + 1] + s1;
        float l2 = d[j * 3 + 2] + s2;
        float hi1 = fmaxf(l0, fmaxf(l1, l2));
        float lo1 = fminf(l0, fminf(l1, l2));
        float mid = l0 + l1 + l2 - hi1 - lo1;
        if (hi1 - mid < THETA) amb = true;
    }
    if (amb) {
        int idx = atomicAdd(&g_fixn, 1);
        if (idx < MAXF) g_fixlist[idx] = t - 1;   // D row to repair
    }
}

// ---------------------------------------------------------------------------
// K3b-fix1: batched full-residual GEMM for flagged rows.
// dfix[f][c] = sum_i ( x*w - rn16(x)*rn16(w) )
// ---------------------------------------------------------------------------
__global__ __launch_bounds__(256) void k_fixgemm(
    const float* __restrict__ xs, const float* __restrict__ Wih)
{
    int n = g_fixn; if (n > MAXF) n = MAXF;
    const int fbase = blockIdx.y * 32;
    if (fbase >= n) return;
    const int c0 = blockIdx.x * 128;
    const int tid = threadIdx.x;

    __shared__ float ws[32][129];    // [k][c]  exact w
    __shared__ float whs[32][129];   // [k][c]  rn16(w)
    __shared__ float xsm[32][33];    // [f][k]  exact x
    __shared__ float xhs[32][33];    // [f][k]  rn16(x)
    __shared__ int tlist[32];

    if (tid < 32) tlist[tid] = (fbase + tid < n) ? g_fixlist[fbase + tid] : -1;
    __syncthreads();

    const int c_loc = tid & 127;
    const int fgrp = (tid >> 7) * 16;

    float acc[16];
#pragma unroll
    for (int f = 0; f < 16; f++) acc[f] = 0.f;

    for (int kc0 = 0; kc0 < I_; kc0 += 32) {
        __syncthreads();
#pragma unroll
        for (int q = 0; q < 16; q++) {
            int lin = q * 256 + tid;
            int c = lin >> 5, k = lin & 31;
            float w = Wih[(size_t)(c0 + c) * I_ + kc0 + k];
            ws[k][c] = w;
            whs[k][c] = __half2float(__float2half_rn(w));
        }
#pragma unroll
        for (int q = 0; q < 4; q++) {
            int lin = q * 256 + tid;
            int f = lin >> 5, k = lin & 31;
            int t1 = tlist[f];
            float xv = (t1 >= 0) ? xs[(size_t)t1 * I_ + kc0 + k] : 0.f;
            xsm[f][k] = xv;
            xhs[f][k] = __half2float(__float2half_rn(xv));
        }
        __syncthreads();

#pragma unroll 4
        for (int k = 0; k < 32; k++) {
            float w = ws[k][c_loc];
            float wh = whs[k][c_loc];
#pragma unroll
            for (int f = 0; f < 16; f++) {
                acc[f] = fmaf(xsm[fgrp + f][k], w, acc[f]);
                acc[f] = fmaf(-xhs[fgrp + f][k], wh, acc[f]);
            }
        }
    }

#pragma unroll
    for (int f = 0; f < 16; f++) {
        int fg = fbase + fgrp + f;
        if (fg < n) g_dfix[(size_t)fg * NCOL + c0 + c_loc] = acc[f];
    }
}

// ---------------------------------------------------------------------------
// K3b-fix2: recompute exact D rows for flagged steps.  grid (MAXF, 3).
// ---------------------------------------------------------------------------
__global__ __launch_bounds__(256) void k_fixD(
    const float* __restrict__ Wsel,
    const float* __restrict__ bih, const float* __restrict__ bhh)
{
    int n = g_fixn; if (n > MAXF) n = MAXF;
    const int fi = blockIdx.x;
    if (fi >= n) return;
    const int t1 = g_fixlist[fi];
    const int j = blockIdx.y;
    const int tid = threadIdx.x;

    const size_t gb = (size_t)t1 * NCOL + (size_t)j * 3 * HD;
    const size_t db = (size_t)fi * NCOL + (size_t)j * 3 * HD;
    const float* bi = bih + (size_t)j * 3 * HD;
    const float* bh = bhh + (size_t)j * 3 * HD;

    float p0 = 0.f, p1 = 0.f, p2 = 0.f;
    for (int o = tid; o < HD; o += 256) {
        float ir  = g_gi[gb + o]          + g_dfix[db + o]          + bi[o]          + bh[o];
        float iz  = g_gi[gb + HD + o]     + g_dfix[db + HD + o]     + bi[HD + o]     + bh[HD + o];
        float inn = g_gi[gb + 2 * HD + o] + g_dfix[db + 2 * HD + o] + bi[2 * HD + o];
        float hn  = bh[2 * HD + o];
        float r = 1.0f / (1.0f + expf(-ir));
        float z = 1.0f / (1.0f + expf(-iz));
        float nn = tanhf(inn + r * hn);
        float h = (1.0f - z) * nn;
        p0 = fmaf(Wsel[0 * WS_ + o], h, p0);
        p1 = fmaf(Wsel[1 * WS_ + o], h, p1);
        p2 = fmaf(Wsel[2 * WS_ + o], h, p2);
    }

    __shared__ float red[3][8];
    int lane = tid & 31, w = tid >> 5;
    float v[3] = {p0, p1, p2};
#pragma unroll
    for (int q = 0; q < 3; q++) {
        float s = v[q];
        for (int off = 16; off > 0; off >>= 1)
            s += __shfl_down_sync(0xffffffffu, s, off);
        if (lane == 0) red[q][w] = s;
    }
    __syncthreads();
    if (tid < 3) {
        float s = 0.f;
#pragma unroll
        for (int ww = 0; ww < 8; ww++) s += red[tid][ww];
        g_D[(size_t)t1 * 9 + j * 3 + tid] = s;
    }
}

// ---------------------------------------------------------------------------
// K3: packed transition maps (after D repair)
// ---------------------------------------------------------------------------
__global__ void k3_f()
{
    int t = blockIdx.x * blockDim.x + threadIdx.x;
    if (t < 1 || t >= T_) return;
    const float* d = g_D + (size_t)(t - 1) * 9;
    float s0 = g_selx[t * 3 + 0];
    float s1 = g_selx[t * 3 + 1];
    float s2 = g_selx[t * 3 + 2];
    unsigned int word = 0;
#pragma unroll
    for (int j = 0; j < 3; j++) {
        float l0 = d[j * 3 + 0] + s0;
        float l1 = d[j * 3 + 1] + s1;
        float l2 = d[j * 3 + 2] + s2;
        int best = 0; float bv = l0;
        if (l1 > bv) { bv = l1; best = 1; }
        if (l2 > bv) { best = 2; }
        word |= (unsigned int)best << (8 * j);
    }
    g_fw[t] = word;
}

// ---------------------------------------------------------------------------
// K4: sequential 3-state automaton composition
// ---------------------------------------------------------------------------
__global__ __launch_bounds__(256) void k4_scan()
{
    __shared__ unsigned int sw[T_];
    for (int i = threadIdx.x; i < T_; i += 256) sw[i] = g_fw[i];
    __syncthreads();
    if (threadIdx.x == 0) {
        int cur = 0;
        g_kk[0] = 0;
        for (int t = 1; t < T_; t++) {
            unsigned int w = sw[t];
            cur = (int)((w >> (cur << 3)) & 0xffu);
            g_kk[t] = cur;
        }
    }
}

// ---------------------------------------------------------------------------
// K5: gather
// ---------------------------------------------------------------------------
__global__ __launch_bounds__(256) void k5_gather(float* __restrict__ out)
{
    int t = blockIdx.x;
    int tt = (t == T_) ? (T_ - 1) : t;
    int sel = g_kk[tt];
    const float4* src = (const float4*)(g_Hall + ((size_t)tt * K_ + sel) * HD);
    float4* dst = (float4*)(out + (size_t)t * HD);
    for (int i = threadIdx.x; i < HD / 4; i += 256) dst[i] = src[i];
}

// ---------------------------------------------------------------------------
extern "C" void kernel_launch(void* const* d_in, const int* in_sizes, int n_in,
                              void* d_out, int out_size)
{
    const float* x    = (const float*)d_in[0];
    const float* Wih  = (const float*)d_in[1];
    // d_in[2] = W_hh : unused (only b_hh enters the math)
    const float* bih  = (const float*)d_in[3];
    const float* bhh  = (const float*)d_in[4];
    const float* Wsel = (const float*)d_in[5];
    const float* bsel = (const float*)d_in[6];
    float* out = (float*)d_out;

    __half *xhi, *whi;
    cudaGetSymbolAddress((void**)&xhi, g_xhi);
    cudaGetSymbolAddress((void**)&whi, g_whi);

    cudaFuncSetAttribute(k1_mma, cudaFuncAttributeMaxDynamicSharedMemorySize, K1_SMEM);

    size_t nx4 = (size_t)T_ * I_ / 4;
    size_t nw4 = (size_t)NCOL * I_ / 4;
    k0_half<<<(int)((nx4 + 255) / 256), 256>>>(x, xhi, nx4);
    k0_half<<<(int)((nw4 + 255) / 256), 256>>>(Wih, whi, nw4);

    dim3 g1(T_ / 128, NCOL / 128);  // M-fast -> A stays L2-resident
    k1_mma<<<g1, 256, K1_SMEM>>>(xhi, whi);

    k_gates<<<(int)(((size_t)T_ * K_ * (HD / 4)) / 256), 256>>>(bih, bhh);
    k2_Dselx<<<T_, 256>>>(x, Wsel, bsel);

    k_zero<<<1, 1>>>();
    k3_flag<<<(T_ + 255) / 256, 256>>>();
    {
        dim3 gf(NCOL / 128, MAXF / 32);
        k_fixgemm<<<gf, 256>>>(x, Wih);
    }
    {
        dim3 gd(MAXF, 3);
        k_fixD<<<gd, 256>>>(Wsel, bih, bhh);
    }
    k3_f<<<(T_ + 255) / 256, 256>>>();
    k4_scan<<<1, 256>>>();
    k5_gather<<<T_ + 1, 256>>>(out);
}

// round 14
// speedup vs baseline: 1.0273x; 1.0273x over previous
#include <cuda_runtime.h>
#include <cuda_fp16.h>
#include <math.h>
#include <stdint.h>

#define T_ 4096
#define I_ 2048
#define HD 2048
#define K_ 3
#define NCOL 18432            // 3*3H
#define WS_ (HD + I_)
#define THETA 4e-3f           // ambiguity threshold on top-2 logit gap (~9.3 sigma)
#define MAXF 128              // max flagged steps (expected ~16)
#define IDMAP 0x020100u       // packed identity map f[j]=j

// ---------------- scratch (device globals) ---------------------------------
__device__ float g_gi[(size_t)T_ * NCOL];        // 1-product GEMM out ~302MB
__device__ float g_Hall[(size_t)T_ * K_ * HD];   // ~100.7MB
__device__ __half g_xhi[(size_t)T_ * I_];
__device__ __half g_whi[(size_t)NCOL * I_];
__device__ float g_D[(size_t)T_ * K_ * K_];
__device__ float g_selx[(size_t)T_ * K_];
__device__ float g_dfix[(size_t)MAXF * NCOL];    // exact corrections for flagged rows
__device__ int g_fixn;
__device__ int g_fixlist[MAXF];
__device__ unsigned int g_fw[T_];
__device__ int g_kk[T_];

// ---------------- helpers ---------------------------------------------------
__device__ __forceinline__ uint32_t smem_u32(const void* p) {
    uint32_t a;
    asm("{ .reg .u64 t; cvta.to.shared.u64 t, %1; cvt.u32.u64 %0, t; }" : "=r"(a) : "l"(p));
    return a;
}
__device__ __forceinline__ void cp16(uint32_t s, const void* g) {
    asm volatile("cp.async.cg.shared.global [%0], [%1], 16;" :: "r"(s), "l"(g));
}
#define CP_COMMIT() asm volatile("cp.async.commit_group;" ::: "memory")
#define CP_WAIT0()  asm volatile("cp.async.wait_group 0;" ::: "memory")

__device__ __forceinline__ void ldsm_x4(uint32_t& r0, uint32_t& r1, uint32_t& r2,
                                        uint32_t& r3, uint32_t a) {
    asm volatile("ldmatrix.sync.aligned.m8n8.x4.shared.b16 {%0,%1,%2,%3}, [%4];"
                 : "=r"(r0), "=r"(r1), "=r"(r2), "=r"(r3) : "r"(a));
}
__device__ __forceinline__ void mma16816(float* d, const uint32_t* a, uint32_t b0, uint32_t b1) {
    asm volatile("mma.sync.aligned.m16n8k16.row.col.f32.f16.f16.f32 "
                 "{%0,%1,%2,%3}, {%4,%5,%6,%7}, {%8,%9}, {%0,%1,%2,%3};"
                 : "+f"(d[0]), "+f"(d[1]), "+f"(d[2]), "+f"(d[3])
                 : "r"(a[0]), "r"(a[1]), "r"(a[2]), "r"(a[3]), "r"(b0), "r"(b1));
}

// fast, saturation-safe sigmoid / tanh (abs err ~1e-7)
__device__ __forceinline__ float fsig(float x)  { return 1.0f / (1.0f + __expf(-x)); }
__device__ __forceinline__ float ftanh(float x) { return 2.0f / (1.0f + __expf(-2.0f * x)) - 1.0f; }

// compose packed 3-byte maps: (g o f)[j] = g[f[j]]
__device__ __forceinline__ unsigned int mcompose(unsigned int g, unsigned int f) {
    unsigned int r = 0;
#pragma unroll
    for (int j = 0; j < 3; j++) {
        unsigned int fj = (f >> (8 * j)) & 3u;
        unsigned int rj = (g >> (8 * fj)) & 3u;
        r |= rj << (8 * j);
    }
    return r;
}

// ---------------------------------------------------------------------------
// K0: fp32 -> fp16 (round-to-nearest)
// ---------------------------------------------------------------------------
__global__ __launch_bounds__(256) void k0_half(
    const float* __restrict__ src, __half* __restrict__ hi, size_t n4)
{
    size_t i = (size_t)blockIdx.x * 256 + threadIdx.x;
    if (i >= n4) return;
    float4 v = *(const float4*)(src + i * 4);
    __half h[4];
    h[0] = __float2half_rn(v.x); h[1] = __float2half_rn(v.y);
    h[2] = __float2half_rn(v.z); h[3] = __float2half_rn(v.w);
    *(uint2*)(hi + i * 4) = *(uint2*)h;
}

// ---------------------------------------------------------------------------
// K1: gi = xhi @ whi^T -- single fp16 HMMA product (R12 configuration:
// 2-stage double buffer, wait_group 0, one __syncthreads per stage).
// ---------------------------------------------------------------------------
#define BK 32
#define ROWB 80
#define TILEB (128 * ROWB)        // 10240
#define STAGEB (2 * TILEB)        // 20480 (A_hi, B_hi)
#define K1_SMEM (2 * STAGEB)      // 40960
#define NS (I_ / BK)              // 64

__global__ void __launch_bounds__(256, 2) k1_mma(
    const __half* __restrict__ xhi, const __half* __restrict__ whi)
{
    extern __shared__ char smem[];
    const uint32_t sbase = smem_u32(smem);
    const int tid = threadIdx.x;
    const int wid = tid >> 5;
    const int lane = tid & 31;

    const int t0 = blockIdx.x * 128;   // M
    const int c0 = blockIdx.y * 128;   // N

    const int warpM = (wid & 3) * 32;
    const int warpN = (wid >> 2) * 64;

    float acc[2][8][4];
#pragma unroll
    for (int i = 0; i < 2; i++)
#pragma unroll
        for (int j = 0; j < 8; j++)
#pragma unroll
            for (int q = 0; q < 4; q++) acc[i][j][q] = 0.f;

    auto fetch = [&](int s) {
        const int stg = s & 1;
        const uint32_t bA_hi = sbase + stg * STAGEB;
        const uint32_t bB_hi = bA_hi + TILEB;
        const int k0 = s * BK;
#pragma unroll
        for (int it = 0; it < 2; it++) {
            int c = it * 256 + tid;
            int kc = c >> 7;
            int row = c & 127;
            uint32_t so = (uint32_t)(row * ROWB + kc * 16);
            size_t ga = (size_t)(t0 + row) * I_ + k0 + kc * 8;
            size_t gb = (size_t)(c0 + row) * I_ + k0 + kc * 8;
            cp16(bA_hi + so, xhi + ga);
            cp16(bB_hi + so, whi + gb);
        }
    };

    fetch(0); CP_COMMIT();

    for (int s = 0; s < NS; s++) {
        CP_WAIT0();
        __syncthreads();

        if (s + 1 < NS) { fetch(s + 1); CP_COMMIT(); }

        const int stg = s & 1;
        const uint32_t bA_hi = sbase + stg * STAGEB;
        const uint32_t bB_hi = bA_hi + TILEB;

#pragma unroll
        for (int kc = 0; kc < 2; kc++) {
            const uint32_t kb = kc * 32 + (lane >> 4) * 16;
            const uint32_t rsel = (lane & 15);

            uint32_t Ah[2][4];
#pragma unroll
            for (int i = 0; i < 2; i++) {
                uint32_t off = (uint32_t)((warpM + i * 16 + rsel) * ROWB) + kb;
                ldsm_x4(Ah[i][0], Ah[i][1], Ah[i][2], Ah[i][3], bA_hi + off);
            }
#pragma unroll
            for (int g = 0; g < 4; g++) {
                uint32_t Bhg[4];
                uint32_t off = (uint32_t)((warpN + g * 16 + rsel) * ROWB) + kb;
                ldsm_x4(Bhg[0], Bhg[1], Bhg[2], Bhg[3], bB_hi + off);
#pragma unroll
                for (int i = 0; i < 2; i++) {
#pragma unroll
                    for (int sel = 0; sel < 2; sel++) {
                        const int j = g * 2 + sel;
                        mma16816(acc[i][j], Ah[i], Bhg[sel], Bhg[sel + 2]);
                    }
                }
            }
        }
    }

#pragma unroll
    for (int i = 0; i < 2; i++) {
#pragma unroll
        for (int j = 0; j < 8; j++) {
            int row = t0 + warpM + i * 16 + (lane >> 2);
            int col = c0 + warpN + j * 8 + (lane & 3) * 2;
            float2 u0 = make_float2(acc[i][j][0], acc[i][j][1]);
            float2 u1 = make_float2(acc[i][j][2], acc[i][j][3]);
            *(float2*)&g_gi[(size_t)row * NCOL + col] = u0;
            *(float2*)&g_gi[(size_t)(row + 8) * NCOL + col] = u1;
        }
    }
}

// ---------------------------------------------------------------------------
// K_GDX: FUSED gates + D + sel_x. Block per t. Computes Hall once (registers),
// writes it, and accumulates the 9 D-dots + 3 selx dots in the same pass --
// eliminates the 100MB Hall re-read that separate k2 paid.
// ---------------------------------------------------------------------------
__global__ __launch_bounds__(256) void k_gdx(
    const float* __restrict__ xs, const float* __restrict__ Wsel,
    const float* __restrict__ bsel,
    const float* __restrict__ bih, const float* __restrict__ bhh)
{
    const int t = blockIdx.x;
    const int tid = threadIdx.x;
    float aD[9] = {0.f, 0.f, 0.f, 0.f, 0.f, 0.f, 0.f, 0.f, 0.f};
    float aS[3] = {0.f, 0.f, 0.f};

    const float* gib = g_gi + (size_t)t * NCOL;
    const float* xrow = xs + (size_t)t * I_;

    for (int o = tid; o < HD; o += 256) {
        float w0 = Wsel[0 * WS_ + o];
        float w1 = Wsel[1 * WS_ + o];
        float w2 = Wsel[2 * WS_ + o];
#pragma unroll
        for (int j = 0; j < 3; j++) {
            const float* gk = gib + (size_t)j * 3 * HD;
            const float* bi = bih + (size_t)j * 3 * HD;
            const float* bh = bhh + (size_t)j * 3 * HD;
            float ir  = gk[o]          + bi[o]          + bh[o];
            float iz  = gk[HD + o]     + bi[HD + o]     + bh[HD + o];
            float inn = gk[2 * HD + o] + bi[2 * HD + o];
            float hn  = bh[2 * HD + o];
            float r = fsig(ir);
            float z = fsig(iz);
            float h = (1.0f - z) * ftanh(inn + r * hn);
            g_Hall[((size_t)t * K_ + j) * HD + o] = h;
            aD[j * 3 + 0] = fmaf(h, w0, aD[j * 3 + 0]);
            aD[j * 3 + 1] = fmaf(h, w1, aD[j * 3 + 1]);
            aD[j * 3 + 2] = fmaf(h, w2, aD[j * 3 + 2]);
        }
    }
    for (int i = tid; i < I_; i += 256) {
        float xv = xrow[i];
        aS[0] = fmaf(xv, Wsel[0 * WS_ + HD + i], aS[0]);
        aS[1] = fmaf(xv, Wsel[1 * WS_ + HD + i], aS[1]);
        aS[2] = fmaf(xv, Wsel[2 * WS_ + HD + i], aS[2]);
    }

    float vals[12];
#pragma unroll
    for (int v = 0; v < 9; v++) vals[v] = aD[v];
#pragma unroll
    for (int v = 0; v < 3; v++) vals[9 + v] = aS[v];

    __shared__ float red[12][8];
    int lane = tid & 31, w = tid >> 5;
#pragma unroll
    for (int v = 0; v < 12; v++) {
        float s = vals[v];
        for (int off = 16; off > 0; off >>= 1)
            s += __shfl_down_sync(0xffffffffu, s, off);
        if (lane == 0) red[v][w] = s;
    }
    __syncthreads();
    if (tid < 12) {
        float s = 0.f;
#pragma unroll
        for (int ww = 0; ww < 8; ww++) s += red[tid][ww];
        if (tid < 9)
            g_D[(size_t)t * 9 + tid] = s;
        else
            g_selx[(size_t)t * 3 + (tid - 9)] = s + bsel[tid - 9];
    }
}

// ---------------------------------------------------------------------------
// reset fix counter (graph replays!)
// ---------------------------------------------------------------------------
__global__ void k_zero() { g_fixn = 0; }

// ---------------------------------------------------------------------------
// K3a: flag ambiguous steps (any j-row with top-2 gap < THETA) -> fixlist
// ---------------------------------------------------------------------------
__global__ void k3_flag()
{
    int t = blockIdx.x * blockDim.x + threadIdx.x;
    if (t < 1 || t >= T_) return;
    const float* d = g_D + (size_t)(t - 1) * 9;
    float s0 = g_selx[t * 3 + 0];
    float s1 = g_selx[t * 3 + 1];
    float s2 = g_selx[t * 3 + 2];
    bool amb = false;
#pragma unroll
    for (int j = 0; j < 3; j++) {
        float l0 = d[j * 3 + 0] + s0;
        float l1 = d[j * 3 + 1] + s1;
        float l2 = d[j * 3 + 2] + s2;
        float hi1 = fmaxf(l0, fmaxf(l1, l2));
        float lo1 = fminf(l0, fminf(l1, l2));
        float mid = l0 + l1 + l2 - hi1 - lo1;
        if (hi1 - mid < THETA) amb = true;
    }
    if (amb) {
        int idx = atomicAdd(&g_fixn, 1);
        if (idx < MAXF) g_fixlist[idx] = t - 1;   // D row to repair
    }
}

// ---------------------------------------------------------------------------
// K3b-fix1: batched full-residual GEMM for flagged rows.
// dfix[f][c] = sum_i ( x*w - rn16(x)*rn16(w) )
// ---------------------------------------------------------------------------
__global__ __launch_bounds__(256) void k_fixgemm(
    const float* __restrict__ xs, const float* __restrict__ Wih)
{
    int n = g_fixn; if (n > MAXF) n = MAXF;
    const int fbase = blockIdx.y * 32;
    if (fbase >= n) return;
    const int c0 = blockIdx.x * 128;
    const int tid = threadIdx.x;

    __shared__ float ws[32][129];
    __shared__ float whs[32][129];
    __shared__ float xsm[32][33];
    __shared__ float xhs[32][33];
    __shared__ int tlist[32];

    if (tid < 32) tlist[tid] = (fbase + tid < n) ? g_fixlist[fbase + tid] : -1;
    __syncthreads();

    const int c_loc = tid & 127;
    const int fgrp = (tid >> 7) * 16;

    float acc[16];
#pragma unroll
    for (int f = 0; f < 16; f++) acc[f] = 0.f;

    for (int kc0 = 0; kc0 < I_; kc0 += 32) {
        __syncthreads();
#pragma unroll
        for (int q = 0; q < 16; q++) {
            int lin = q * 256 + tid;
            int c = lin >> 5, k = lin & 31;
            float w = Wih[(size_t)(c0 + c) * I_ + kc0 + k];
            ws[k][c] = w;
            whs[k][c] = __half2float(__float2half_rn(w));
        }
#pragma unroll
        for (int q = 0; q < 4; q++) {
            int lin = q * 256 + tid;
            int f = lin >> 5, k = lin & 31;
            int t1 = tlist[f];
            float xv = (t1 >= 0) ? xs[(size_t)t1 * I_ + kc0 + k] : 0.f;
            xsm[f][k] = xv;
            xhs[f][k] = __half2float(__float2half_rn(xv));
        }
        __syncthreads();

#pragma unroll 4
        for (int k = 0; k < 32; k++) {
            float w = ws[k][c_loc];
            float wh = whs[k][c_loc];
#pragma unroll
            for (int f = 0; f < 16; f++) {
                acc[f] = fmaf(xsm[fgrp + f][k], w, acc[f]);
                acc[f] = fmaf(-xhs[fgrp + f][k], wh, acc[f]);
            }
        }
    }

#pragma unroll
    for (int f = 0; f < 16; f++) {
        int fg = fbase + fgrp + f;
        if (fg < n) g_dfix[(size_t)fg * NCOL + c0 + c_loc] = acc[f];
    }
}

// ---------------------------------------------------------------------------
// K3b-fix2: recompute exact D rows for flagged steps.  grid (MAXF, 3).
// ---------------------------------------------------------------------------
__global__ __launch_bounds__(256) void k_fixD(
    const float* __restrict__ Wsel,
    const float* __restrict__ bih, const float* __restrict__ bhh)
{
    int n = g_fixn; if (n > MAXF) n = MAXF;
    const int fi = blockIdx.x;
    if (fi >= n) return;
    const int t1 = g_fixlist[fi];
    const int j = blockIdx.y;
    const int tid = threadIdx.x;

    const size_t gb = (size_t)t1 * NCOL + (size_t)j * 3 * HD;
    const size_t db = (size_t)fi * NCOL + (size_t)j * 3 * HD;
    const float* bi = bih + (size_t)j * 3 * HD;
    const float* bh = bhh + (size_t)j * 3 * HD;

    float p0 = 0.f, p1 = 0.f, p2 = 0.f;
    for (int o = tid; o < HD; o += 256) {
        float ir  = g_gi[gb + o]          + g_dfix[db + o]          + bi[o]          + bh[o];
        float iz  = g_gi[gb + HD + o]     + g_dfix[db + HD + o]     + bi[HD + o]     + bh[HD + o];
        float inn = g_gi[gb + 2 * HD + o] + g_dfix[db + 2 * HD + o] + bi[2 * HD + o];
        float hn  = bh[2 * HD + o];
        float r = 1.0f / (1.0f + expf(-ir));
        float z = 1.0f / (1.0f + expf(-iz));
        float nn = tanhf(inn + r * hn);
        float h = (1.0f - z) * nn;
        p0 = fmaf(Wsel[0 * WS_ + o], h, p0);
        p1 = fmaf(Wsel[1 * WS_ + o], h, p1);
        p2 = fmaf(Wsel[2 * WS_ + o], h, p2);
    }

    __shared__ float red[3][8];
    int lane = tid & 31, w = tid >> 5;
    float v[3] = {p0, p1, p2};
#pragma unroll
    for (int q = 0; q < 3; q++) {
        float s = v[q];
        for (int off = 16; off > 0; off >>= 1)
            s += __shfl_down_sync(0xffffffffu, s, off);
        if (lane == 0) red[q][w] = s;
    }
    __syncthreads();
    if (tid < 3) {
        float s = 0.f;
#pragma unroll
        for (int ww = 0; ww < 8; ww++) s += red[tid][ww];
        g_D[(size_t)t1 * 9 + j * 3 + tid] = s;
    }
}

// ---------------------------------------------------------------------------
// K3: packed transition maps (after D repair)
// ---------------------------------------------------------------------------
__global__ void k3_f()
{
    int t = blockIdx.x * blockDim.x + threadIdx.x;
    if (t < 1 || t >= T_) return;
    const float* d = g_D + (size_t)(t - 1) * 9;
    float s0 = g_selx[t * 3 + 0];
    float s1 = g_selx[t * 3 + 1];
    float s2 = g_selx[t * 3 + 2];
    unsigned int word = 0;
#pragma unroll
    for (int j = 0; j < 3; j++) {
        float l0 = d[j * 3 + 0] + s0;
        float l1 = d[j * 3 + 1] + s1;
        float l2 = d[j * 3 + 2] + s2;
        int best = 0; float bv = l0;
        if (l1 > bv) { bv = l1; best = 1; }
        if (l2 > bv) { best = 2; }
        word |= (unsigned int)best << (8 * j);
    }
    g_fw[t] = word;
}

// ---------------------------------------------------------------------------
// K4: parallel function-composition scan (Hillis-Steele over packed maps).
// 1 block x 1024 threads, 4 maps/thread.  kk[4a+i] = c_i[P_a(0)].
// ---------------------------------------------------------------------------
__global__ __launch_bounds__(1024) void k4_scan()
{
    __shared__ unsigned int comp[1024];
    const int tid = threadIdx.x;

    // load 4 consecutive maps; m for t=0 is the identity (kk[0]=0 by def)
    uint4 raw = *(const uint4*)&g_fw[tid * 4];
    unsigned int m0 = (tid == 0) ? IDMAP : raw.x;
    unsigned int m1 = raw.y, m2 = raw.z, m3 = raw.w;

    // segment-local inclusive composites
    unsigned int c0 = m0;
    unsigned int c1 = mcompose(m1, c0);
    unsigned int c2 = mcompose(m2, c1);
    unsigned int c3 = mcompose(m3, c2);

    comp[tid] = c3;
    __syncthreads();

    // inclusive scan over segment composites
    for (int off = 1; off < 1024; off <<= 1) {
        unsigned int self = comp[tid];
        unsigned int u = (tid >= off) ? comp[tid - off] : IDMAP;
        __syncthreads();
        comp[tid] = mcompose(self, u);
        __syncthreads();
    }

    // exclusive prefix for this segment, applied to initial state 0
    unsigned int P = (tid == 0) ? IDMAP : comp[tid - 1];
    unsigned int s0 = P & 3u;

    int4 o;
    o.x = (int)((c0 >> (8 * s0)) & 3u);
    o.y = (int)((c1 >> (8 * s0)) & 3u);
    o.z = (int)((c2 >> (8 * s0)) & 3u);
    o.w = (int)((c3 >> (8 * s0)) & 3u);
    *(int4*)&g_kk[tid * 4] = o;
}

// ---------------------------------------------------------------------------
// K5: gather
// ---------------------------------------------------------------------------
__global__ __launch_bounds__(256) void k5_gather(float* __restrict__ out)
{
    int t = blockIdx.x;
    int tt = (t == T_) ? (T_ - 1) : t;
    int sel = g_kk[tt];
    const float4* src = (const float4*)(g_Hall + ((size_t)tt * K_ + sel) * HD);
    float4* dst = (float4*)(out + (size_t)t * HD);
    for (int i = threadIdx.x; i < HD / 4; i += 256) dst[i] = src[i];
}

// ---------------------------------------------------------------------------
extern "C" void kernel_launch(void* const* d_in, const int* in_sizes, int n_in,
                              void* d_out, int out_size)
{
    const float* x    = (const float*)d_in[0];
    const float* Wih  = (const float*)d_in[1];
    // d_in[2] = W_hh : unused (only b_hh enters the math)
    const float* bih  = (const float*)d_in[3];
    const float* bhh  = (const float*)d_in[4];
    const float* Wsel = (const float*)d_in[5];
    const float* bsel = (const float*)d_in[6];
    float* out = (float*)d_out;

    __half *xhi, *whi;
    cudaGetSymbolAddress((void**)&xhi, g_xhi);
    cudaGetSymbolAddress((void**)&whi, g_whi);

    cudaFuncSetAttribute(k1_mma, cudaFuncAttributeMaxDynamicSharedMemorySize, K1_SMEM);

    size_t nx4 = (size_t)T_ * I_ / 4;
    size_t nw4 = (size_t)NCOL * I_ / 4;
    k0_half<<<(int)((nx4 + 255) / 256), 256>>>(x, xhi, nx4);
    k0_half<<<(int)((nw4 + 255) / 256), 256>>>(Wih, whi, nw4);

    dim3 g1(T_ / 128, NCOL / 128);  // M-fast -> A stays L2-resident
    k1_mma<<<g1, 256, K1_SMEM>>>(xhi, whi);

    k_gdx<<<T_, 256>>>(x, Wsel, bsel, bih, bhh);   // fused gates + D + selx

    k_zero<<<1, 1>>>();
    k3_flag<<<(T_ + 255) / 256, 256>>>();
    {
        dim3 gf(NCOL / 128, MAXF / 32);
        k_fixgemm<<<gf, 256>>>(x, Wih);
    }
    {
        dim3 gd(MAXF, 3);
        k_fixD<<<gd, 256>>>(Wsel, bih, bhh);
    }
    k3_f<<<(T_ + 255) / 256, 256>>>();
    k4_scan<<<1, 1024>>>();
    k5_gather<<<T_ + 1, 256>>>(out);
}

// round 15
// speedup vs baseline: 1.0715x; 1.0430x over previous
#include <cuda_runtime.h>
#include <cuda_fp16.h>
#include <math.h>
#include <stdint.h>

#define T_ 4096
#define I_ 2048
#define HD 2048
#define K_ 3
#define NCOL 18432            // 3*3H
#define WS_ (HD + I_)
#define THETA 4e-3f           // ambiguity threshold on top-2 logit gap (~8 sigma)
#define MAXF 128              // max flagged steps (expected ~20)
#define IDMAP 0x020100u       // packed identity map f[j]=j

// ---------------- scratch (device globals) ---------------------------------
__device__ __half g_gi[(size_t)T_ * NCOL];       // 1-product GEMM out, fp16 ~151MB
__device__ float g_Hall[(size_t)T_ * K_ * HD];   // ~100.7MB
__device__ __half g_xhi[(size_t)T_ * I_];
__device__ __half g_whi[(size_t)NCOL * I_];
__device__ float g_D[(size_t)T_ * K_ * K_];
__device__ float g_selx[(size_t)T_ * K_];
__device__ float g_dfix[(size_t)MAXF * NCOL];    // EXACT gi rows for flagged steps
__device__ int g_fixn;
__device__ int g_fixlist[MAXF];
__device__ unsigned int g_fw[T_];
__device__ int g_kk[T_];

// ---------------- helpers ---------------------------------------------------
__device__ __forceinline__ uint32_t smem_u32(const void* p) {
    uint32_t a;
    asm("{ .reg .u64 t; cvta.to.shared.u64 t, %1; cvt.u32.u64 %0, t; }" : "=r"(a) : "l"(p));
    return a;
}
__device__ __forceinline__ void cp16(uint32_t s, const void* g) {
    asm volatile("cp.async.cg.shared.global [%0], [%1], 16;" :: "r"(s), "l"(g));
}
#define CP_COMMIT() asm volatile("cp.async.commit_group;" ::: "memory")
#define CP_WAIT0()  asm volatile("cp.async.wait_group 0;" ::: "memory")

__device__ __forceinline__ void ldsm_x4(uint32_t& r0, uint32_t& r1, uint32_t& r2,
                                        uint32_t& r3, uint32_t a) {
    asm volatile("ldmatrix.sync.aligned.m8n8.x4.shared.b16 {%0,%1,%2,%3}, [%4];"
                 : "=r"(r0), "=r"(r1), "=r"(r2), "=r"(r3) : "r"(a));
}
__device__ __forceinline__ void mma16816(float* d, const uint32_t* a, uint32_t b0, uint32_t b1) {
    asm volatile("mma.sync.aligned.m16n8k16.row.col.f32.f16.f16.f32 "
                 "{%0,%1,%2,%3}, {%4,%5,%6,%7}, {%8,%9}, {%0,%1,%2,%3};"
                 : "+f"(d[0]), "+f"(d[1]), "+f"(d[2]), "+f"(d[3])
                 : "r"(a[0]), "r"(a[1]), "r"(a[2]), "r"(a[3]), "r"(b0), "r"(b1));
}

// fast, saturation-safe sigmoid / tanh (abs err ~1e-7)
__device__ __forceinline__ float fsig(float x)  { return 1.0f / (1.0f + __expf(-x)); }
__device__ __forceinline__ float ftanh(float x) { return 2.0f / (1.0f + __expf(-2.0f * x)) - 1.0f; }

// compose packed 3-byte maps: (g o f)[j] = g[f[j]]
__device__ __forceinline__ unsigned int mcompose(unsigned int g, unsigned int f) {
    unsigned int r = 0;
#pragma unroll
    for (int j = 0; j < 3; j++) {
        unsigned int fj = (f >> (8 * j)) & 3u;
        unsigned int rj = (g >> (8 * fj)) & 3u;
        r |= rj << (8 * j);
    }
    return r;
}

// ---------------------------------------------------------------------------
// K0: fp32 -> fp16 (round-to-nearest)
// ---------------------------------------------------------------------------
__global__ __launch_bounds__(256) void k0_half(
    const float* __restrict__ src, __half* __restrict__ hi, size_t n4)
{
    size_t i = (size_t)blockIdx.x * 256 + threadIdx.x;
    if (i >= n4) return;
    float4 v = *(const float4*)(src + i * 4);
    __half h[4];
    h[0] = __float2half_rn(v.x); h[1] = __float2half_rn(v.y);
    h[2] = __float2half_rn(v.z); h[3] = __float2half_rn(v.w);
    *(uint2*)(hi + i * 4) = *(uint2*)h;
}

// ---------------------------------------------------------------------------
// K1: gi = xhi @ whi^T -- single fp16 HMMA product, fp16 OUTPUT.
// R12 pipeline config (2-stage double buffer, one __syncthreads per stage).
// ---------------------------------------------------------------------------
#define BK 32
#define ROWB 80
#define TILEB (128 * ROWB)        // 10240
#define STAGEB (2 * TILEB)        // 20480 (A_hi, B_hi)
#define K1_SMEM (2 * STAGEB)      // 40960
#define NS (I_ / BK)              // 64

__global__ void __launch_bounds__(256, 2) k1_mma(
    const __half* __restrict__ xhi, const __half* __restrict__ whi)
{
    extern __shared__ char smem[];
    const uint32_t sbase = smem_u32(smem);
    const int tid = threadIdx.x;
    const int wid = tid >> 5;
    const int lane = tid & 31;

    const int t0 = blockIdx.x * 128;   // M
    const int c0 = blockIdx.y * 128;   // N

    const int warpM = (wid & 3) * 32;
    const int warpN = (wid >> 2) * 64;

    float acc[2][8][4];
#pragma unroll
    for (int i = 0; i < 2; i++)
#pragma unroll
        for (int j = 0; j < 8; j++)
#pragma unroll
            for (int q = 0; q < 4; q++) acc[i][j][q] = 0.f;

    auto fetch = [&](int s) {
        const int stg = s & 1;
        const uint32_t bA_hi = sbase + stg * STAGEB;
        const uint32_t bB_hi = bA_hi + TILEB;
        const int k0 = s * BK;
#pragma unroll
        for (int it = 0; it < 2; it++) {
            int c = it * 256 + tid;
            int kc = c >> 7;
            int row = c & 127;
            uint32_t so = (uint32_t)(row * ROWB + kc * 16);
            size_t ga = (size_t)(t0 + row) * I_ + k0 + kc * 8;
            size_t gb = (size_t)(c0 + row) * I_ + k0 + kc * 8;
            cp16(bA_hi + so, xhi + ga);
            cp16(bB_hi + so, whi + gb);
        }
    };

    fetch(0); CP_COMMIT();

    for (int s = 0; s < NS; s++) {
        CP_WAIT0();
        __syncthreads();

        if (s + 1 < NS) { fetch(s + 1); CP_COMMIT(); }

        const int stg = s & 1;
        const uint32_t bA_hi = sbase + stg * STAGEB;
        const uint32_t bB_hi = bA_hi + TILEB;

#pragma unroll
        for (int kc = 0; kc < 2; kc++) {
            const uint32_t kb = kc * 32 + (lane >> 4) * 16;
            const uint32_t rsel = (lane & 15);

            uint32_t Ah[2][4];
#pragma unroll
            for (int i = 0; i < 2; i++) {
                uint32_t off = (uint32_t)((warpM + i * 16 + rsel) * ROWB) + kb;
                ldsm_x4(Ah[i][0], Ah[i][1], Ah[i][2], Ah[i][3], bA_hi + off);
            }
#pragma unroll
            for (int g = 0; g < 4; g++) {
                uint32_t Bhg[4];
                uint32_t off = (uint32_t)((warpN + g * 16 + rsel) * ROWB) + kb;
                ldsm_x4(Bhg[0], Bhg[1], Bhg[2], Bhg[3], bB_hi + off);
#pragma unroll
                for (int i = 0; i < 2; i++) {
#pragma unroll
                    for (int sel = 0; sel < 2; sel++) {
                        const int j = g * 2 + sel;
                        mma16816(acc[i][j], Ah[i], Bhg[sel], Bhg[sel + 2]);
                    }
                }
            }
        }
    }

    // epilogue: fp32 acc -> fp16 gi
#pragma unroll
    for (int i = 0; i < 2; i++) {
#pragma unroll
        for (int j = 0; j < 8; j++) {
            int row = t0 + warpM + i * 16 + (lane >> 2);
            int col = c0 + warpN + j * 8 + (lane & 3) * 2;
            __half2 u0 = __floats2half2_rn(acc[i][j][0], acc[i][j][1]);
            __half2 u1 = __floats2half2_rn(acc[i][j][2], acc[i][j][3]);
            *(__half2*)&g_gi[(size_t)row * NCOL + col] = u0;
            *(__half2*)&g_gi[(size_t)(row + 8) * NCOL + col] = u1;
        }
    }
}

// ---------------------------------------------------------------------------
// K_GDX: FUSED gates + D + sel_x, VECTORIZED (4 outputs/thread-iter, uint2
// fp16 gi loads + float4 bias/weight loads).
// ---------------------------------------------------------------------------
__global__ __launch_bounds__(256) void k_gdx(
    const float* __restrict__ xs, const float* __restrict__ Wsel,
    const float* __restrict__ bsel,
    const float* __restrict__ bih, const float* __restrict__ bhh)
{
    const int t = blockIdx.x;
    const int tid = threadIdx.x;
    float aD[9] = {0.f, 0.f, 0.f, 0.f, 0.f, 0.f, 0.f, 0.f, 0.f};
    float aS[3] = {0.f, 0.f, 0.f};

    const __half* gib = g_gi + (size_t)t * NCOL;
    const float* xrow = xs + (size_t)t * I_;

    for (int o4 = tid; o4 < HD / 4; o4 += 256) {
        const int o = o4 * 4;
        float4 w0 = *(const float4*)&Wsel[0 * WS_ + o];
        float4 w1 = *(const float4*)&Wsel[1 * WS_ + o];
        float4 w2 = *(const float4*)&Wsel[2 * WS_ + o];
        float ww0[4] = {w0.x, w0.y, w0.z, w0.w};
        float ww1[4] = {w1.x, w1.y, w1.z, w1.w};
        float ww2[4] = {w2.x, w2.y, w2.z, w2.w};
#pragma unroll
        for (int j = 0; j < 3; j++) {
            const __half* gk = gib + (size_t)j * 3 * HD;
            const float* bi = bih + (size_t)j * 3 * HD;
            const float* bh = bhh + (size_t)j * 3 * HD;
            // 4 halves per gate row
            uint2 hr_ = *(const uint2*)&gk[o];
            uint2 hz_ = *(const uint2*)&gk[HD + o];
            uint2 hn_ = *(const uint2*)&gk[2 * HD + o];
            float2 ir01 = __half22float2(*(const __half2*)&hr_.x);
            float2 ir23 = __half22float2(*(const __half2*)&hr_.y);
            float2 iz01 = __half22float2(*(const __half2*)&hz_.x);
            float2 iz23 = __half22float2(*(const __half2*)&hz_.y);
            float2 in01 = __half22float2(*(const __half2*)&hn_.x);
            float2 in23 = __half22float2(*(const __half2*)&hn_.y);
            float4 br = *(const float4*)&bi[o];
            float4 bz = *(const float4*)&bi[HD + o];
            float4 bn = *(const float4*)&bi[2 * HD + o];
            float4 cr = *(const float4*)&bh[o];
            float4 cz = *(const float4*)&bh[HD + o];
            float4 cn = *(const float4*)&bh[2 * HD + o];

            float irv[4] = {ir01.x + br.x + cr.x, ir01.y + br.y + cr.y,
                            ir23.x + br.z + cr.z, ir23.y + br.w + cr.w};
            float izv[4] = {iz01.x + bz.x + cz.x, iz01.y + bz.y + cz.y,
                            iz23.x + bz.z + cz.z, iz23.y + bz.w + cz.w};
            float inv[4] = {in01.x + bn.x, in01.y + bn.y,
                            in23.x + bn.z, in23.y + bn.w};
            float hnv[4] = {cn.x, cn.y, cn.z, cn.w};

            float hres[4];
#pragma unroll
            for (int q = 0; q < 4; q++) {
                float r = fsig(irv[q]);
                float z = fsig(izv[q]);
                hres[q] = (1.0f - z) * ftanh(inv[q] + r * hnv[q]);
            }
            float4 hout = make_float4(hres[0], hres[1], hres[2], hres[3]);
            *(float4*)&g_Hall[((size_t)t * K_ + j) * HD + o] = hout;
#pragma unroll
            for (int q = 0; q < 4; q++) {
                aD[j * 3 + 0] = fmaf(hres[q], ww0[q], aD[j * 3 + 0]);
                aD[j * 3 + 1] = fmaf(hres[q], ww1[q], aD[j * 3 + 1]);
                aD[j * 3 + 2] = fmaf(hres[q], ww2[q], aD[j * 3 + 2]);
            }
        }
    }
    for (int i4 = tid; i4 < I_ / 4; i4 += 256) {
        const int i = i4 * 4;
        float4 xv = *(const float4*)&xrow[i];
        float4 u0 = *(const float4*)&Wsel[0 * WS_ + HD + i];
        float4 u1 = *(const float4*)&Wsel[1 * WS_ + HD + i];
        float4 u2 = *(const float4*)&Wsel[2 * WS_ + HD + i];
        aS[0] += xv.x * u0.x + xv.y * u0.y + xv.z * u0.z + xv.w * u0.w;
        aS[1] += xv.x * u1.x + xv.y * u1.y + xv.z * u1.z + xv.w * u1.w;
        aS[2] += xv.x * u2.x + xv.y * u2.y + xv.z * u2.z + xv.w * u2.w;
    }

    float vals[12];
#pragma unroll
    for (int v = 0; v < 9; v++) vals[v] = aD[v];
#pragma unroll
    for (int v = 0; v < 3; v++) vals[9 + v] = aS[v];

    __shared__ float red[12][8];
    int lane = tid & 31, w = tid >> 5;
#pragma unroll
    for (int v = 0; v < 12; v++) {
        float s = vals[v];
        for (int off = 16; off > 0; off >>= 1)
            s += __shfl_down_sync(0xffffffffu, s, off);
        if (lane == 0) red[v][w] = s;
    }
    __syncthreads();
    if (tid < 12) {
        float s = 0.f;
#pragma unroll
        for (int ww = 0; ww < 8; ww++) s += red[tid][ww];
        if (tid < 9)
            g_D[(size_t)t * 9 + tid] = s;
        else
            g_selx[(size_t)t * 3 + (tid - 9)] = s + bsel[tid - 9];
    }
}

// ---------------------------------------------------------------------------
// reset fix counter (graph replays!)
// ---------------------------------------------------------------------------
__global__ void k_zero() { g_fixn = 0; }

// ---------------------------------------------------------------------------
// K3a: flag ambiguous steps (any j-row with top-2 gap < THETA) -> fixlist
// ---------------------------------------------------------------------------
__global__ void k3_flag()
{
    int t = blockIdx.x * blockDim.x + threadIdx.x;
    if (t < 1 || t >= T_) return;
    const float* d = g_D + (size_t)(t - 1) * 9;
    float s0 = g_selx[t * 3 + 0];
    float s1 = g_selx[t * 3 + 1];
    float s2 = g_selx[t * 3 + 2];
    bool amb = false;
#pragma unroll
    for (int j = 0; j < 3; j++) {
        float l0 = d[j * 3 + 0] + s0;
        float l1 = d[j * 3 + 1] + s1;
        float l2 = d[j * 3 + 2] + s2;
        float hi1 = fmaxf(l0, fmaxf(l1, l2));
        float lo1 = fminf(l0, fminf(l1, l2));
        float mid = l0 + l1 + l2 - hi1 - lo1;
        if (hi1 - mid < THETA) amb = true;
    }
    if (amb) {
        int idx = atomicAdd(&g_fixn, 1);
        if (idx < MAXF) g_fixlist[idx] = t - 1;   // D row to repair
    }
}

// ---------------------------------------------------------------------------
// K3b-fix1: batched EXACT-row GEMM for flagged rows.
// dfix[f][c] = sum_i x[t1[f]][i] * W[c][i]   (full fp32 dot; independent of
// gi storage precision -> repaired D rows are exact)
// ---------------------------------------------------------------------------
__global__ __launch_bounds__(256) void k_fixgemm(
    const float* __restrict__ xs, const float* __restrict__ Wih)
{
    int n = g_fixn; if (n > MAXF) n = MAXF;
    const int fbase = blockIdx.y * 32;
    if (fbase >= n) return;
    const int c0 = blockIdx.x * 128;
    const int tid = threadIdx.x;

    __shared__ float ws[32][129];    // [k][c]
    __shared__ float xsm[32][33];    // [f][k]
    __shared__ int tlist[32];

    if (tid < 32) tlist[tid] = (fbase + tid < n) ? g_fixlist[fbase + tid] : -1;
    __syncthreads();

    const int c_loc = tid & 127;
    const int fgrp = (tid >> 7) * 16;

    float acc[16];
#pragma unroll
    for (int f = 0; f < 16; f++) acc[f] = 0.f;

    for (int kc0 = 0; kc0 < I_; kc0 += 32) {
        __syncthreads();
#pragma unroll
        for (int q = 0; q < 16; q++) {
            int lin = q * 256 + tid;
            int c = lin >> 5, k = lin & 31;
            ws[k][c] = Wih[(size_t)(c0 + c) * I_ + kc0 + k];
        }
#pragma unroll
        for (int q = 0; q < 4; q++) {
            int lin = q * 256 + tid;
            int f = lin >> 5, k = lin & 31;
            int t1 = tlist[f];
            xsm[f][k] = (t1 >= 0) ? xs[(size_t)t1 * I_ + kc0 + k] : 0.f;
        }
        __syncthreads();

#pragma unroll 4
        for (int k = 0; k < 32; k++) {
            float w = ws[k][c_loc];
#pragma unroll
            for (int f = 0; f < 16; f++)
                acc[f] = fmaf(xsm[fgrp + f][k], w, acc[f]);
        }
    }

#pragma unroll
    for (int f = 0; f < 16; f++) {
        int fg = fbase + fgrp + f;
        if (fg < n) g_dfix[(size_t)fg * NCOL + c0 + c_loc] = acc[f];
    }
}

// ---------------------------------------------------------------------------
// K3b-fix2: recompute exact D rows for flagged steps from dfix (exact gi).
// grid (MAXF, 3).
// ---------------------------------------------------------------------------
__global__ __launch_bounds__(256) void k_fixD(
    const float* __restrict__ Wsel,
    const float* __restrict__ bih, const float* __restrict__ bhh)
{
    int n = g_fixn; if (n > MAXF) n = MAXF;
    const int fi = blockIdx.x;
    if (fi >= n) return;
    const int t1 = g_fixlist[fi];
    const int j = blockIdx.y;
    const int tid = threadIdx.x;

    const size_t db = (size_t)fi * NCOL + (size_t)j * 3 * HD;
    const float* bi = bih + (size_t)j * 3 * HD;
    const float* bh = bhh + (size_t)j * 3 * HD;

    float p0 = 0.f, p1 = 0.f, p2 = 0.f;
    for (int o = tid; o < HD; o += 256) {
        float ir  = g_dfix[db + o]          + bi[o]          + bh[o];
        float iz  = g_dfix[db + HD + o]     + bi[HD + o]     + bh[HD + o];
        float inn = g_dfix[db + 2 * HD + o] + bi[2 * HD + o];
        float hn  = bh[2 * HD + o];
        float r = 1.0f / (1.0f + expf(-ir));
        float z = 1.0f / (1.0f + expf(-iz));
        float nn = tanhf(inn + r * hn);
        float h = (1.0f - z) * nn;
        p0 = fmaf(Wsel[0 * WS_ + o], h, p0);
        p1 = fmaf(Wsel[1 * WS_ + o], h, p1);
        p2 = fmaf(Wsel[2 * WS_ + o], h, p2);
    }

    __shared__ float red[3][8];
    int lane = tid & 31, w = tid >> 5;
    float v[3] = {p0, p1, p2};
#pragma unroll
    for (int q = 0; q < 3; q++) {
        float s = v[q];
        for (int off = 16; off > 0; off >>= 1)
            s += __shfl_down_sync(0xffffffffu, s, off);
        if (lane == 0) red[q][w] = s;
    }
    __syncthreads();
    if (tid < 3) {
        float s = 0.f;
#pragma unroll
        for (int ww = 0; ww < 8; ww++) s += red[tid][ww];
        g_D[(size_t)t1 * 9 + j * 3 + tid] = s;
    }
}

// ---------------------------------------------------------------------------
// K3: packed transition maps (after D repair)
// ---------------------------------------------------------------------------
__global__ void k3_f()
{
    int t = blockIdx.x * blockDim.x + threadIdx.x;
    if (t < 1 || t >= T_) return;
    const float* d = g_D + (size_t)(t - 1) * 9;
    float s0 = g_selx[t * 3 + 0];
    float s1 = g_selx[t * 3 + 1];
    float s2 = g_selx[t * 3 + 2];
    unsigned int word = 0;
#pragma unroll
    for (int j = 0; j < 3; j++) {
        float l0 = d[j * 3 + 0] + s0;
        float l1 = d[j * 3 + 1] + s1;
        float l2 = d[j * 3 + 2] + s2;
        int best = 0; float bv = l0;
        if (l1 > bv) { bv = l1; best = 1; }
        if (l2 > bv) { best = 2; }
        word |= (unsigned int)best << (8 * j);
    }
    g_fw[t] = word;
}

// ---------------------------------------------------------------------------
// K4: parallel function-composition scan (Hillis-Steele over packed maps).
// ---------------------------------------------------------------------------
__global__ __launch_bounds__(1024) void k4_scan()
{
    __shared__ unsigned int comp[1024];
    const int tid = threadIdx.x;

    uint4 raw = *(const uint4*)&g_fw[tid * 4];
    unsigned int m0 = (tid == 0) ? IDMAP : raw.x;
    unsigned int m1 = raw.y, m2 = raw.z, m3 = raw.w;

    unsigned int c0 = m0;
    unsigned int c1 = mcompose(m1, c0);
    unsigned int c2 = mcompose(m2, c1);
    unsigned int c3 = mcompose(m3, c2);

    comp[tid] = c3;
    __syncthreads();

    for (int off = 1; off < 1024; off <<= 1) {
        unsigned int self = comp[tid];
        unsigned int u = (tid >= off) ? comp[tid - off] : IDMAP;
        __syncthreads();
        comp[tid] = mcompose(self, u);
        __syncthreads();
    }

    unsigned int P = (tid == 0) ? IDMAP : comp[tid - 1];
    unsigned int s0 = P & 3u;

    int4 o;
    o.x = (int)((c0 >> (8 * s0)) & 3u);
    o.y = (int)((c1 >> (8 * s0)) & 3u);
    o.z = (int)((c2 >> (8 * s0)) & 3u);
    o.w = (int)((c3 >> (8 * s0)) & 3u);
    *(int4*)&g_kk[tid * 4] = o;
}

// ---------------------------------------------------------------------------
// K5: gather
// ---------------------------------------------------------------------------
__global__ __launch_bounds__(256) void k5_gather(float* __restrict__ out)
{
    int t = blockIdx.x;
    int tt = (t == T_) ? (T_ - 1) : t;
    int sel = g_kk[tt];
    const float4* src = (const float4*)(g_Hall + ((size_t)tt * K_ + sel) * HD);
    float4* dst = (float4*)(out + (size_t)t * HD);
    for (int i = threadIdx.x; i < HD / 4; i += 256) dst[i] = src[i];
}

// ---------------------------------------------------------------------------
extern "C" void kernel_launch(void* const* d_in, const int* in_sizes, int n_in,
                              void* d_out, int out_size)
{
    const float* x    = (const float*)d_in[0];
    const float* Wih  = (const float*)d_in[1];
    // d_in[2] = W_hh : unused (only b_hh enters the math)
    const float* bih  = (const float*)d_in[3];
    const float* bhh  = (const float*)d_in[4];
    const float* Wsel = (const float*)d_in[5];
    const float* bsel = (const float*)d_in[6];
    float* out = (float*)d_out;

    __half *xhi, *whi;
    cudaGetSymbolAddress((void**)&xhi, g_xhi);
    cudaGetSymbolAddress((void**)&whi, g_whi);

    cudaFuncSetAttribute(k1_mma, cudaFuncAttributeMaxDynamicSharedMemorySize, K1_SMEM);

    size_t nx4 = (size_t)T_ * I_ / 4;
    size_t nw4 = (size_t)NCOL * I_ / 4;
    k0_half<<<(int)((nx4 + 255) / 256), 256>>>(x, xhi, nx4);
    k0_half<<<(int)((nw4 + 255) / 256), 256>>>(Wih, whi, nw4);

    dim3 g1(T_ / 128, NCOL / 128);  // M-fast -> A stays L2-resident
    k1_mma<<<g1, 256, K1_SMEM>>>(xhi, whi);

    k_gdx<<<T_, 256>>>(x, Wsel, bsel, bih, bhh);   // fused gates + D + selx

    k_zero<<<1, 1>>>();
    k3_flag<<<(T_ + 255) / 256, 256>>>();
    {
        dim3 gf(NCOL / 128, MAXF / 32);
        k_fixgemm<<<gf, 256>>>(x, Wih);
    }
    {
        dim3 gd(MAXF, 3);
        k_fixD<<<gd, 256>>>(Wsel, bih, bhh);
    }
    k3_f<<<(T_ + 255) / 256, 256>>>();
    k4_scan<<<1, 1024>>>();
    k5_gather<<<T_ + 1, 256>>>(out);
}

// round 16
// speedup vs baseline: 1.5578x; 1.4538x over previous
#include <cuda_runtime.h>
#include <cuda_fp16.h>
#include <math.h>
#include <stdint.h>

#define T_ 4096
#define I_ 2048
#define HD 2048
#define K_ 3
#define NCOL 18432            // 3*3H
#define WS_ (HD + I_)
#define THETA 4e-3f           // ambiguity threshold on top-2 logit gap (~8 sigma)
#define MAXF 128              // max flagged steps (expected ~20)
#define IDMAP 0x020100u       // packed identity map f[j]=j

// ---------------- scratch (device globals) ---------------------------------
__device__ __half g_gi[(size_t)T_ * NCOL];       // GEMM out, fp16 ~151MB
__device__ __half g_Hall[(size_t)T_ * K_ * HD];  // fp16 ~50MB
__device__ __half g_xhi[(size_t)T_ * I_];
__device__ __half g_whi[(size_t)NCOL * I_];
__device__ float g_D[(size_t)T_ * K_ * K_];
__device__ float g_selx[(size_t)T_ * K_];
__device__ float g_dfix[(size_t)MAXF * NCOL];    // EXACT gi rows for flagged steps
__device__ int g_fixn;
__device__ int g_fixlist[MAXF];
__device__ unsigned int g_fw[T_];
__device__ int g_kk[T_];

// ---------------- helpers ---------------------------------------------------
__device__ __forceinline__ uint32_t smem_u32(const void* p) {
    uint32_t a;
    asm("{ .reg .u64 t; cvta.to.shared.u64 t, %1; cvt.u32.u64 %0, t; }" : "=r"(a) : "l"(p));
    return a;
}
__device__ __forceinline__ void cp16(uint32_t s, const void* g) {
    asm volatile("cp.async.cg.shared.global [%0], [%1], 16;" :: "r"(s), "l"(g));
}
#define CP_COMMIT() asm volatile("cp.async.commit_group;" ::: "memory")
#define CP_WAIT0()  asm volatile("cp.async.wait_group 0;" ::: "memory")

__device__ __forceinline__ void ldsm_x4(uint32_t& r0, uint32_t& r1, uint32_t& r2,
                                        uint32_t& r3, uint32_t a) {
    asm volatile("ldmatrix.sync.aligned.m8n8.x4.shared.b16 {%0,%1,%2,%3}, [%4];"
                 : "=r"(r0), "=r"(r1), "=r"(r2), "=r"(r3) : "r"(a));
}
__device__ __forceinline__ void mma16816(float* d, const uint32_t* a, uint32_t b0, uint32_t b1) {
    asm volatile("mma.sync.aligned.m16n8k16.row.col.f32.f16.f16.f32 "
                 "{%0,%1,%2,%3}, {%4,%5,%6,%7}, {%8,%9}, {%0,%1,%2,%3};"
                 : "+f"(d[0]), "+f"(d[1]), "+f"(d[2]), "+f"(d[3])
                 : "r"(a[0]), "r"(a[1]), "r"(a[2]), "r"(a[3]), "r"(b0), "r"(b1));
}

// fast, saturation-safe sigmoid / tanh (abs err ~1e-7)
__device__ __forceinline__ float fsig(float x)  { return 1.0f / (1.0f + __expf(-x)); }
__device__ __forceinline__ float ftanh(float x) { return 2.0f / (1.0f + __expf(-2.0f * x)) - 1.0f; }

// compose packed 3-byte maps: (g o f)[j] = g[f[j]]
__device__ __forceinline__ unsigned int mcompose(unsigned int g, unsigned int f) {
    unsigned int r = 0;
#pragma unroll
    for (int j = 0; j < 3; j++) {
        unsigned int fj = (f >> (8 * j)) & 3u;
        unsigned int rj = (g >> (8 * fj)) & 3u;
        r |= rj << (8 * j);
    }
    return r;
}

// ---------------------------------------------------------------------------
// K0: fp32 -> fp16 (round-to-nearest)
// ---------------------------------------------------------------------------
__global__ __launch_bounds__(256) void k0_half(
    const float* __restrict__ src, __half* __restrict__ hi, size_t n4)
{
    size_t i = (size_t)blockIdx.x * 256 + threadIdx.x;
    if (i >= n4) return;
    float4 v = *(const float4*)(src + i * 4);
    __half h[4];
    h[0] = __float2half_rn(v.x); h[1] = __float2half_rn(v.y);
    h[2] = __float2half_rn(v.z); h[3] = __float2half_rn(v.w);
    *(uint2*)(hi + i * 4) = *(uint2*)h;
}

// ---------------------------------------------------------------------------
// K1: gi = xhi @ whi^T -- single fp16 HMMA product, fp16 output.
// BK=64: 32 stages (half the barriers of BK=32), double-buffered cp.async.
// Rows padded to 144B (128B data + 16B) -> conflict-free ldsm & STS.
// ---------------------------------------------------------------------------
#define BK 64
#define ROWB 144
#define TILEB (128 * ROWB)        // 18432
#define STAGEB (2 * TILEB)        // 36864 (A, B)
#define K1_SMEM (2 * STAGEB)      // 73728
#define NS (I_ / BK)              // 32

__global__ void __launch_bounds__(256, 2) k1_mma(
    const __half* __restrict__ xhi, const __half* __restrict__ whi)
{
    extern __shared__ char smem[];
    const uint32_t sbase = smem_u32(smem);
    const int tid = threadIdx.x;
    const int wid = tid >> 5;
    const int lane = tid & 31;

    const int t0 = blockIdx.x * 128;   // M
    const int c0 = blockIdx.y * 128;   // N

    const int warpM = (wid & 3) * 32;
    const int warpN = (wid >> 2) * 64;

    float acc[2][8][4];
#pragma unroll
    for (int i = 0; i < 2; i++)
#pragma unroll
        for (int j = 0; j < 8; j++)
#pragma unroll
            for (int q = 0; q < 4; q++) acc[i][j][q] = 0.f;

    auto fetch = [&](int s) {
        const int stg = s & 1;
        const uint32_t bA = sbase + stg * STAGEB;
        const uint32_t bB = bA + TILEB;
        const int k0 = s * BK;
#pragma unroll
        for (int it = 0; it < 8; it++) {
            int c = it * 256 + tid;          // 0..2047
            int tilesel = c >> 10;           // 0:A 1:B
            int r = (c >> 3) & 127;
            int kc = c & 7;                  // 16B chunk within 128B row
            uint32_t so = (uint32_t)(r * ROWB + kc * 16);
            if (tilesel == 0)
                cp16(bA + so, xhi + (size_t)(t0 + r) * I_ + k0 + kc * 8);
            else
                cp16(bB + so, whi + (size_t)(c0 + r) * I_ + k0 + kc * 8);
        }
    };

    fetch(0); CP_COMMIT();

    for (int s = 0; s < NS; s++) {
        CP_WAIT0();
        __syncthreads();

        if (s + 1 < NS) { fetch(s + 1); CP_COMMIT(); }

        const int stg = s & 1;
        const uint32_t bA = sbase + stg * STAGEB;
        const uint32_t bB = bA + TILEB;

#pragma unroll
        for (int kc = 0; kc < 4; kc++) {     // 4 x 16-half quarters of BK=64
            const uint32_t kb = kc * 32 + (lane >> 4) * 16;
            const uint32_t rsel = (lane & 15);

            uint32_t Ah[2][4];
#pragma unroll
            for (int i = 0; i < 2; i++) {
                uint32_t off = (uint32_t)((warpM + i * 16 + rsel) * ROWB) + kb;
                ldsm_x4(Ah[i][0], Ah[i][1], Ah[i][2], Ah[i][3], bA + off);
            }
#pragma unroll
            for (int g = 0; g < 4; g++) {
                uint32_t Bhg[4];
                uint32_t off = (uint32_t)((warpN + g * 16 + rsel) * ROWB) + kb;
                ldsm_x4(Bhg[0], Bhg[1], Bhg[2], Bhg[3], bB + off);
#pragma unroll
                for (int i = 0; i < 2; i++) {
#pragma unroll
                    for (int sel = 0; sel < 2; sel++) {
                        const int j = g * 2 + sel;
                        mma16816(acc[i][j], Ah[i], Bhg[sel], Bhg[sel + 2]);
                    }
                }
            }
        }
    }

    // epilogue: fp32 acc -> fp16 gi
#pragma unroll
    for (int i = 0; i < 2; i++) {
#pragma unroll
        for (int j = 0; j < 8; j++) {
            int row = t0 + warpM + i * 16 + (lane >> 2);
            int col = c0 + warpN + j * 8 + (lane & 3) * 2;
            __half2 u0 = __floats2half2_rn(acc[i][j][0], acc[i][j][1]);
            __half2 u1 = __floats2half2_rn(acc[i][j][2], acc[i][j][3]);
            *(__half2*)&g_gi[(size_t)row * NCOL + col] = u0;
            *(__half2*)&g_gi[(size_t)(row + 8) * NCOL + col] = u1;
        }
    }
}

// ---------------------------------------------------------------------------
// K_GDX: FUSED gates + D + sel_x. 512 threads, exactly ONE o4-chunk and one
// selx-chunk per thread (no loops) -> better latency hiding. Hall stored fp16.
// ---------------------------------------------------------------------------
__global__ __launch_bounds__(512) void k_gdx(
    const float* __restrict__ xs, const float* __restrict__ Wsel,
    const float* __restrict__ bsel,
    const float* __restrict__ bih, const float* __restrict__ bhh)
{
    const int t = blockIdx.x;
    const int tid = threadIdx.x;
    float aD[9] = {0.f, 0.f, 0.f, 0.f, 0.f, 0.f, 0.f, 0.f, 0.f};
    float aS[3];

    const __half* gib = g_gi + (size_t)t * NCOL;
    const float* xrow = xs + (size_t)t * I_;

    {
        const int o = tid * 4;                 // HD/4 == 512 == blockDim
        float4 w0 = *(const float4*)&Wsel[0 * WS_ + o];
        float4 w1 = *(const float4*)&Wsel[1 * WS_ + o];
        float4 w2 = *(const float4*)&Wsel[2 * WS_ + o];
        float ww0[4] = {w0.x, w0.y, w0.z, w0.w};
        float ww1[4] = {w1.x, w1.y, w1.z, w1.w};
        float ww2[4] = {w2.x, w2.y, w2.z, w2.w};
#pragma unroll
        for (int j = 0; j < 3; j++) {
            const __half* gk = gib + (size_t)j * 3 * HD;
            const float* bi = bih + (size_t)j * 3 * HD;
            const float* bh = bhh + (size_t)j * 3 * HD;
            uint2 hr_ = *(const uint2*)&gk[o];
            uint2 hz_ = *(const uint2*)&gk[HD + o];
            uint2 hn_ = *(const uint2*)&gk[2 * HD + o];
            float2 ir01 = __half22float2(*(const __half2*)&hr_.x);
            float2 ir23 = __half22float2(*(const __half2*)&hr_.y);
            float2 iz01 = __half22float2(*(const __half2*)&hz_.x);
            float2 iz23 = __half22float2(*(const __half2*)&hz_.y);
            float2 in01 = __half22float2(*(const __half2*)&hn_.x);
            float2 in23 = __half22float2(*(const __half2*)&hn_.y);
            float4 br = *(const float4*)&bi[o];
            float4 bz = *(const float4*)&bi[HD + o];
            float4 bn = *(const float4*)&bi[2 * HD + o];
            float4 cr = *(const float4*)&bh[o];
            float4 cz = *(const float4*)&bh[HD + o];
            float4 cn = *(const float4*)&bh[2 * HD + o];

            float irv[4] = {ir01.x + br.x + cr.x, ir01.y + br.y + cr.y,
                            ir23.x + br.z + cr.z, ir23.y + br.w + cr.w};
            float izv[4] = {iz01.x + bz.x + cz.x, iz01.y + bz.y + cz.y,
                            iz23.x + bz.z + cz.z, iz23.y + bz.w + cz.w};
            float inv[4] = {in01.x + bn.x, in01.y + bn.y,
                            in23.x + bn.z, in23.y + bn.w};
            float hnv[4] = {cn.x, cn.y, cn.z, cn.w};

            float hres[4];
#pragma unroll
            for (int q = 0; q < 4; q++) {
                float r = fsig(irv[q]);
                float z = fsig(izv[q]);
                hres[q] = (1.0f - z) * ftanh(inv[q] + r * hnv[q]);
            }
            uint2 hpack;
            *(__half2*)&hpack.x = __floats2half2_rn(hres[0], hres[1]);
            *(__half2*)&hpack.y = __floats2half2_rn(hres[2], hres[3]);
            *(uint2*)&g_Hall[((size_t)t * K_ + j) * HD + o] = hpack;
#pragma unroll
            for (int q = 0; q < 4; q++) {
                aD[j * 3 + 0] = fmaf(hres[q], ww0[q], aD[j * 3 + 0]);
                aD[j * 3 + 1] = fmaf(hres[q], ww1[q], aD[j * 3 + 1]);
                aD[j * 3 + 2] = fmaf(hres[q], ww2[q], aD[j * 3 + 2]);
            }
        }
    }
    {
        const int i = tid * 4;                 // I_/4 == 512 == blockDim
        float4 xv = *(const float4*)&xrow[i];
        float4 u0 = *(const float4*)&Wsel[0 * WS_ + HD + i];
        float4 u1 = *(const float4*)&Wsel[1 * WS_ + HD + i];
        float4 u2 = *(const float4*)&Wsel[2 * WS_ + HD + i];
        aS[0] = xv.x * u0.x + xv.y * u0.y + xv.z * u0.z + xv.w * u0.w;
        aS[1] = xv.x * u1.x + xv.y * u1.y + xv.z * u1.z + xv.w * u1.w;
        aS[2] = xv.x * u2.x + xv.y * u2.y + xv.z * u2.z + xv.w * u2.w;
    }

    float vals[12];
#pragma unroll
    for (int v = 0; v < 9; v++) vals[v] = aD[v];
#pragma unroll
    for (int v = 0; v < 3; v++) vals[9 + v] = aS[v];

    __shared__ float red[12][16];
    int lane = tid & 31, w = tid >> 5;
#pragma unroll
    for (int v = 0; v < 12; v++) {
        float s = vals[v];
        for (int off = 16; off > 0; off >>= 1)
            s += __shfl_down_sync(0xffffffffu, s, off);
        if (lane == 0) red[v][w] = s;
    }
    __syncthreads();
    if (tid < 12) {
        float s = 0.f;
#pragma unroll
        for (int ww = 0; ww < 16; ww++) s += red[tid][ww];
        if (tid < 9)
            g_D[(size_t)t * 9 + tid] = s;
        else
            g_selx[(size_t)t * 3 + (tid - 9)] = s + bsel[tid - 9];
    }
}

// ---------------------------------------------------------------------------
// reset fix counter (graph replays!)
// ---------------------------------------------------------------------------
__global__ void k_zero() { g_fixn = 0; }

// ---------------------------------------------------------------------------
// K3a: flag ambiguous steps (any j-row with top-2 gap < THETA) -> fixlist
// ---------------------------------------------------------------------------
__global__ void k3_flag()
{
    int t = blockIdx.x * blockDim.x + threadIdx.x;
    if (t < 1 || t >= T_) return;
    const float* d = g_D + (size_t)(t - 1) * 9;
    float s0 = g_selx[t * 3 + 0];
    float s1 = g_selx[t * 3 + 1];
    float s2 = g_selx[t * 3 + 2];
    bool amb = false;
#pragma unroll
    for (int j = 0; j < 3; j++) {
        float l0 = d[j * 3 + 0] + s0;
        float l1 = d[j * 3 + 1] + s1;
        float l2 = d[j * 3 + 2] + s2;
        float hi1 = fmaxf(l0, fmaxf(l1, l2));
        float lo1 = fminf(l0, fminf(l1, l2));
        float mid = l0 + l1 + l2 - hi1 - lo1;
        if (hi1 - mid < THETA) amb = true;
    }
    if (amb) {
        int idx = atomicAdd(&g_fixn, 1);
        if (idx < MAXF) g_fixlist[idx] = t - 1;   // D row to repair
    }
}

// ---------------------------------------------------------------------------
// K3b-fix1: batched EXACT-row GEMM for flagged rows.
// dfix[f][c] = sum_i x[t1[f]][i] * W[c][i]
// ---------------------------------------------------------------------------
__global__ __launch_bounds__(256) void k_fixgemm(
    const float* __restrict__ xs, const float* __restrict__ Wih)
{
    int n = g_fixn; if (n > MAXF) n = MAXF;
    const int fbase = blockIdx.y * 32;
    if (fbase >= n) return;
    const int c0 = blockIdx.x * 128;
    const int tid = threadIdx.x;

    __shared__ float ws[32][129];    // [k][c]
    __shared__ float xsm[32][33];    // [f][k]
    __shared__ int tlist[32];

    if (tid < 32) tlist[tid] = (fbase + tid < n) ? g_fixlist[fbase + tid] : -1;
    __syncthreads();

    const int c_loc = tid & 127;
    const int fgrp = (tid >> 7) * 16;

    float acc[16];
#pragma unroll
    for (int f = 0; f < 16; f++) acc[f] = 0.f;

    for (int kc0 = 0; kc0 < I_; kc0 += 32) {
        __syncthreads();
#pragma unroll
        for (int q = 0; q < 16; q++) {
            int lin = q * 256 + tid;
            int c = lin >> 5, k = lin & 31;
            ws[k][c] = Wih[(size_t)(c0 + c) * I_ + kc0 + k];
        }
#pragma unroll
        for (int q = 0; q < 4; q++) {
            int lin = q * 256 + tid;
            int f = lin >> 5, k = lin & 31;
            int t1 = tlist[f];
            xsm[f][k] = (t1 >= 0) ? xs[(size_t)t1 * I_ + kc0 + k] : 0.f;
        }
        __syncthreads();

#pragma unroll 4
        for (int k = 0; k < 32; k++) {
            float w = ws[k][c_loc];
#pragma unroll
            for (int f = 0; f < 16; f++)
                acc[f] = fmaf(xsm[fgrp + f][k], w, acc[f]);
        }
    }

#pragma unroll
    for (int f = 0; f < 16; f++) {
        int fg = fbase + fgrp + f;
        if (fg < n) g_dfix[(size_t)fg * NCOL + c0 + c_loc] = acc[f];
    }
}

// ---------------------------------------------------------------------------
// K3b-fix2: recompute exact D rows for flagged steps from dfix (exact gi).
// grid (MAXF, 3).
// ---------------------------------------------------------------------------
__global__ __launch_bounds__(256) void k_fixD(
    const float* __restrict__ Wsel,
    const float* __restrict__ bih, const float* __restrict__ bhh)
{
    int n = g_fixn; if (n > MAXF) n = MAXF;
    const int fi = blockIdx.x;
    if (fi >= n) return;
    const int t1 = g_fixlist[fi];
    const int j = blockIdx.y;
    const int tid = threadIdx.x;

    const size_t db = (size_t)fi * NCOL + (size_t)j * 3 * HD;
    const float* bi = bih + (size_t)j * 3 * HD;
    const float* bh = bhh + (size_t)j * 3 * HD;

    float p0 = 0.f, p1 = 0.f, p2 = 0.f;
    for (int o = tid; o < HD; o += 256) {
        float ir  = g_dfix[db + o]          + bi[o]          + bh[o];
        float iz  = g_dfix[db + HD + o]     + bi[HD + o]     + bh[HD + o];
        float inn = g_dfix[db + 2 * HD + o] + bi[2 * HD + o];
        float hn  = bh[2 * HD + o];
        float r = 1.0f / (1.0f + expf(-ir));
        float z = 1.0f / (1.0f + expf(-iz));
        float nn = tanhf(inn + r * hn);
        float h = (1.0f - z) * nn;
        p0 = fmaf(Wsel[0 * WS_ + o], h, p0);
        p1 = fmaf(Wsel[1 * WS_ + o], h, p1);
        p2 = fmaf(Wsel[2 * WS_ + o], h, p2);
    }

    __shared__ float red[3][8];
    int lane = tid & 31, w = tid >> 5;
    float v[3] = {p0, p1, p2};
#pragma unroll
    for (int q = 0; q < 3; q++) {
        float s = v[q];
        for (int off = 16; off > 0; off >>= 1)
            s += __shfl_down_sync(0xffffffffu, s, off);
        if (lane == 0) red[q][w] = s;
    }
    __syncthreads();
    if (tid < 3) {
        float s = 0.f;
#pragma unroll
        for (int ww = 0; ww < 8; ww++) s += red[tid][ww];
        g_D[(size_t)t1 * 9 + j * 3 + tid] = s;
    }
}

// ---------------------------------------------------------------------------
// K3: packed transition maps (after D repair)
// ---------------------------------------------------------------------------
__global__ void k3_f()
{
    int t = blockIdx.x * blockDim.x + threadIdx.x;
    if (t < 1 || t >= T_) return;
    const float* d = g_D + (size_t)(t - 1) * 9;
    float s0 = g_selx[t * 3 + 0];
    float s1 = g_selx[t * 3 + 1];
    float s2 = g_selx[t * 3 + 2];
    unsigned int word = 0;
#pragma unroll
    for (int j = 0; j < 3; j++) {
        float l0 = d[j * 3 + 0] + s0;
        float l1 = d[j * 3 + 1] + s1;
        float l2 = d[j * 3 + 2] + s2;
        int best = 0; float bv = l0;
        if (l1 > bv) { bv = l1; best = 1; }
        if (l2 > bv) { best = 2; }
        word |= (unsigned int)best << (8 * j);
    }
    g_fw[t] = word;
}

// ---------------------------------------------------------------------------
// K4: parallel function-composition scan (Hillis-Steele over packed maps).
// ---------------------------------------------------------------------------
__global__ __launch_bounds__(1024) void k4_scan()
{
    __shared__ unsigned int comp[1024];
    const int tid = threadIdx.x;

    uint4 raw = *(const uint4*)&g_fw[tid * 4];
    unsigned int m0 = (tid == 0) ? IDMAP : raw.x;
    unsigned int m1 = raw.y, m2 = raw.z, m3 = raw.w;

    unsigned int c0 = m0;
    unsigned int c1 = mcompose(m1, c0);
    unsigned int c2 = mcompose(m2, c1);
    unsigned int c3 = mcompose(m3, c2);

    comp[tid] = c3;
    __syncthreads();

    for (int off = 1; off < 1024; off <<= 1) {
        unsigned int self = comp[tid];
        unsigned int u = (tid >= off) ? comp[tid - off] : IDMAP;
        __syncthreads();
        comp[tid] = mcompose(self, u);
        __syncthreads();
    }

    unsigned int P = (tid == 0) ? IDMAP : comp[tid - 1];
    unsigned int s0 = P & 3u;

    int4 o;
    o.x = (int)((c0 >> (8 * s0)) & 3u);
    o.y = (int)((c1 >> (8 * s0)) & 3u);
    o.z = (int)((c2 >> (8 * s0)) & 3u);
    o.w = (int)((c3 >> (8 * s0)) & 3u);
    *(int4*)&g_kk[tid * 4] = o;
}

// ---------------------------------------------------------------------------
// K5: gather (fp16 Hall -> fp32 out)
// ---------------------------------------------------------------------------
__global__ __launch_bounds__(256) void k5_gather(float* __restrict__ out)
{
    int t = blockIdx.x;
    int tt = (t == T_) ? (T_ - 1) : t;
    int sel = g_kk[tt];
    const __half* src = g_Hall + ((size_t)tt * K_ + sel) * HD;
    float* dst = out + (size_t)t * HD;
    for (int i = threadIdx.x; i < HD / 4; i += 256) {
        uint2 raw = *(const uint2*)&src[i * 4];
        float2 a = __half22float2(*(const __half2*)&raw.x);
        float2 b = __half22float2(*(const __half2*)&raw.y);
        float4 o = make_float4(a.x, a.y, b.x, b.y);
        *(float4*)&dst[i * 4] = o;
    }
}

// ---------------------------------------------------------------------------
extern "C" void kernel_launch(void* const* d_in, const int* in_sizes, int n_in,
                              void* d_out, int out_size)
{
    const float* x    = (const float*)d_in[0];
    const float* Wih  = (const float*)d_in[1];
    // d_in[2] = W_hh : unused (only b_hh enters the math)
    const float* bih  = (const float*)d_in[3];
    const float* bhh  = (const float*)d_in[4];
    const float* Wsel = (const float*)d_in[5];
    const float* bsel = (const float*)d_in[6];
    float* out = (float*)d_out;

    __half *xhi, *whi;
    cudaGetSymbolAddress((void**)&xhi, g_xhi);
    cudaGetSymbolAddress((void**)&whi, g_whi);

    cudaFuncSetAttribute(k1_mma, cudaFuncAttributeMaxDynamicSharedMemorySize, K1_SMEM);

    size_t nx4 = (size_t)T_ * I_ / 4;
    size_t nw4 = (size_t)NCOL * I_ / 4;
    k0_half<<<(int)((nx4 + 255) / 256), 256>>>(x, xhi, nx4);
    k0_half<<<(int)((nw4 + 255) / 256), 256>>>(Wih, whi, nw4);

    dim3 g1(T_ / 128, NCOL / 128);  // M-fast -> A stays L2-resident
    k1_mma<<<g1, 256, K1_SMEM>>>(xhi, whi);

    k_gdx<<<T_, 512>>>(x, Wsel, bsel, bih, bhh);   // fused gates + D + selx

    k_zero<<<1, 1>>>();
    k3_flag<<<(T_ + 255) / 256, 256>>>();
    {
        dim3 gf(NCOL / 128, MAXF / 32);
        k_fixgemm<<<gf, 256>>>(x, Wih);
    }
    {
        dim3 gd(MAXF, 3);
        k_fixD<<<gd, 256>>>(Wsel, bih, bhh);
    }
    k3_f<<<(T_ + 255) / 256, 256>>>();
    k4_scan<<<1, 1024>>>();
    k5_gather<<<T_ + 1, 256>>>(out);
}

// round 17
// speedup vs baseline: 1.5992x; 1.0265x over previous
#include <cuda_runtime.h>
#include <cuda_fp16.h>
#include <math.h>
#include <stdint.h>

#define T_ 4096
#define I_ 2048
#define HD 2048
#define K_ 3
#define NCOL 18432            // 3*3H = 2048 o * 9 gates
#define WS_ (HD + I_)
#define THETA 4e-3f           // ambiguity threshold on top-2 logit gap (~8 sigma)
#define MAXF 128
#define IDMAP 0x020100u

// ---------------- scratch (device globals) ---------------------------------
__device__ __half g_Hall[(size_t)T_ * K_ * HD];  // fp16 ~50MB
__device__ __half g_xhi[(size_t)T_ * I_];
__device__ __half g_whi[(size_t)NCOL * I_];      // PERMUTED rows: c' = o*9+j*3+g
__device__ float g_D[(size_t)T_ * K_ * K_];
__device__ float g_selx[(size_t)T_ * K_];
__device__ float g_dfix[(size_t)MAXF * NCOL];    // EXACT gi rows (ORIGINAL layout)
__device__ int g_fixn;
__device__ int g_fixlist[MAXF];
__device__ unsigned int g_fw[T_];
__device__ int g_kk[T_];

// ---------------- helpers ---------------------------------------------------
__device__ __forceinline__ uint32_t smem_u32(const void* p) {
    uint32_t a;
    asm("{ .reg .u64 t; cvta.to.shared.u64 t, %1; cvt.u32.u64 %0, t; }" : "=r"(a) : "l"(p));
    return a;
}
__device__ __forceinline__ void cp16(uint32_t s, const void* g) {
    asm volatile("cp.async.cg.shared.global [%0], [%1], 16;" :: "r"(s), "l"(g));
}
#define CP_COMMIT() asm volatile("cp.async.commit_group;" ::: "memory")
#define CP_WAIT0()  asm volatile("cp.async.wait_group 0;" ::: "memory")

__device__ __forceinline__ void ldsm_x4(uint32_t& r0, uint32_t& r1, uint32_t& r2,
                                        uint32_t& r3, uint32_t a) {
    asm volatile("ldmatrix.sync.aligned.m8n8.x4.shared.b16 {%0,%1,%2,%3}, [%4];"
                 : "=r"(r0), "=r"(r1), "=r"(r2), "=r"(r3) : "r"(a));
}
__device__ __forceinline__ void mma16816(float* d, const uint32_t* a, uint32_t b0, uint32_t b1) {
    asm volatile("mma.sync.aligned.m16n8k16.row.col.f32.f16.f16.f32 "
                 "{%0,%1,%2,%3}, {%4,%5,%6,%7}, {%8,%9}, {%0,%1,%2,%3};"
                 : "+f"(d[0]), "+f"(d[1]), "+f"(d[2]), "+f"(d[3])
                 : "r"(a[0]), "r"(a[1]), "r"(a[2]), "r"(a[3]), "r"(b0), "r"(b1));
}

__device__ __forceinline__ float fsig(float x)  { return 1.0f / (1.0f + __expf(-x)); }
__device__ __forceinline__ float ftanh(float x) { return 2.0f / (1.0f + __expf(-2.0f * x)) - 1.0f; }

__device__ __forceinline__ unsigned int mcompose(unsigned int g, unsigned int f) {
    unsigned int r = 0;
#pragma unroll
    for (int j = 0; j < 3; j++) {
        unsigned int fj = (f >> (8 * j)) & 3u;
        unsigned int rj = (g >> (8 * fj)) & 3u;
        r |= rj << (8 * j);
    }
    return r;
}

// ---------------------------------------------------------------------------
// K0a: x -> fp16
// ---------------------------------------------------------------------------
__global__ __launch_bounds__(256) void k0_half(
    const float* __restrict__ src, __half* __restrict__ hi, size_t n4)
{
    size_t i = (size_t)blockIdx.x * 256 + threadIdx.x;
    if (i >= n4) return;
    float4 v = *(const float4*)(src + i * 4);
    __half h[4];
    h[0] = __float2half_rn(v.x); h[1] = __float2half_rn(v.y);
    h[2] = __float2half_rn(v.z); h[3] = __float2half_rn(v.w);
    *(uint2*)(hi + i * 4) = *(uint2*)h;
}

// ---------------------------------------------------------------------------
// K0b: W -> fp16 with ROW PERMUTATION: whi row c' = o*9 + r  takes original
// W row r*HD + o  (r = j*3+g).  Consecutive-i access stays fully coalesced.
// ---------------------------------------------------------------------------
__global__ __launch_bounds__(256) void k0_wperm(
    const float* __restrict__ W, __half* __restrict__ whi)
{
    size_t idx = (size_t)blockIdx.x * 256 + threadIdx.x;   // over NCOL * I_/4
    if (idx >= (size_t)NCOL * (I_ / 4)) return;
    int cp = (int)(idx >> 9);          // /(I_/4)=512
    int i  = ((int)idx & 511) * 4;
    int o = cp / 9;
    int r = cp - o * 9;
    const float* src = W + ((size_t)r * HD + o) * I_ + i;
    float4 v = *(const float4*)src;
    __half h[4];
    h[0] = __float2half_rn(v.x); h[1] = __float2half_rn(v.y);
    h[2] = __float2half_rn(v.z); h[3] = __float2half_rn(v.w);
    *(uint2*)(whi + (size_t)cp * I_ + i) = *(uint2*)h;
}

// ---------------------------------------------------------------------------
// zero D accumulators (atomic targets) -- every replay
// ---------------------------------------------------------------------------
__global__ void k_zeroD()
{
    int i = blockIdx.x * 256 + threadIdx.x;
    if (i < T_ * 9) g_D[i] = 0.f;
}

// ---------------------------------------------------------------------------
// K1: fused GEMM + gates + Hall + D-partials.
// Tile M=128 x N=144 (16 o-groups x 9 gates) x BK=64.  8 warps, each 1 m16
// row-slab x full 144 cols (9 ldsm-B groups, 18 MMAs per kc).
// Epilogue: acc -> smem (reuses operand buffers) -> gates on fp32 acc ->
// fp16 Hall + atomicAdd D partials.
// ---------------------------------------------------------------------------
#define BK 64
#define ROWB 144              // 128B data + 16B pad
#define TILEA (128 * ROWB)    // 18432
#define TILEB_ (144 * ROWB)   // 20736
#define STAGEB (TILEA + TILEB_)  // 39168
#define ESTRIDE 148
#define K1_SMEM (2 * STAGEB)  // 78336 >= 128*148*4 + 336*4 = 77120
#define NS (I_ / BK)          // 32

__global__ void __launch_bounds__(256, 2) k1_mma(
    const __half* __restrict__ xhi, const __half* __restrict__ whi,
    const float* __restrict__ Wsel,
    const float* __restrict__ bih, const float* __restrict__ bhh)
{
    extern __shared__ char smem[];
    const uint32_t sbase = smem_u32(smem);
    const int tid = threadIdx.x;
    const int wid = tid >> 5;
    const int lane = tid & 31;

    const int t0 = blockIdx.x * 128;      // M
    const int c0 = blockIdx.y * 144;      // N (permuted cols)
    const int warpM = wid * 16;

    float acc[18][4];
#pragma unroll
    for (int j = 0; j < 18; j++)
#pragma unroll
        for (int q = 0; q < 4; q++) acc[j][q] = 0.f;

    auto fetch = [&](int s) {
        const int stg = s & 1;
        const uint32_t bA = sbase + stg * STAGEB;
        const uint32_t bB = bA + TILEA;
        const int k0 = s * BK;
#pragma unroll
        for (int it = 0; it < 9; it++) {
            int c = it * 256 + tid;            // 0..2303, use 2176
            if (c < 1024) {
                int r = c >> 3, kc = c & 7;
                cp16(bA + (uint32_t)(r * ROWB + kc * 16),
                     xhi + (size_t)(t0 + r) * I_ + k0 + kc * 8);
            } else if (c < 2176) {
                int c2 = c - 1024;
                int r = c2 >> 3, kc = c2 & 7;
                cp16(bB + (uint32_t)(r * ROWB + kc * 16),
                     whi + (size_t)(c0 + r) * I_ + k0 + kc * 8);
            }
        }
    };

    fetch(0); CP_COMMIT();

    for (int s = 0; s < NS; s++) {
        CP_WAIT0();
        __syncthreads();

        if (s + 1 < NS) { fetch(s + 1); CP_COMMIT(); }

        const int stg = s & 1;
        const uint32_t bA = sbase + stg * STAGEB;
        const uint32_t bB = bA + TILEA;

#pragma unroll
        for (int kc = 0; kc < 4; kc++) {
            const uint32_t kb = kc * 32 + (lane >> 4) * 16;
            const uint32_t rsel = (lane & 15);

            uint32_t Ah[4];
            ldsm_x4(Ah[0], Ah[1], Ah[2], Ah[3],
                    bA + (uint32_t)((warpM + rsel) * ROWB) + kb);
#pragma unroll
            for (int g = 0; g < 9; g++) {
                uint32_t Bg[4];
                ldsm_x4(Bg[0], Bg[1], Bg[2], Bg[3],
                        bB + (uint32_t)((g * 16 + rsel) * ROWB) + kb);
                mma16816(acc[g * 2 + 0], Ah, Bg[0], Bg[2]);
                mma16816(acc[g * 2 + 1], Ah, Bg[1], Bg[3]);
            }
        }
    }

    // ---------------- epilogue: gates + Hall + D partials -------------------
    __syncthreads();                       // all warps done reading operands
    float* e = (float*)smem;               // 128 x ESTRIDE fp32 C-tile
    float* bsm = e + 128 * ESTRIDE;        // 288 floats: [o16][j3][g3][2]
    float* wsm = bsm + 288;                // 48 floats:  [k3][o16]

    // STS accumulators
    {
        int rA = warpM + (lane >> 2);
#pragma unroll
        for (int j = 0; j < 18; j++) {
            int col = j * 8 + (lane & 3) * 2;
            e[rA * ESTRIDE + col]     = acc[j][0];
            e[rA * ESTRIDE + col + 1] = acc[j][1];
            e[(rA + 8) * ESTRIDE + col]     = acc[j][2];
            e[(rA + 8) * ESTRIDE + col + 1] = acc[j][3];
        }
    }
    // stage biases + Wsel for this o-group
    for (int q = tid; q < 288; q += 256) {
        int o = q / 18, rem = q % 18;
        int j = rem / 6, g = (rem % 6) / 2, which = rem & 1;
        int og = blockIdx.y * 16 + o;
        size_t bidx = (size_t)(j * 3 + g) * HD + og;
        bsm[q] = which ? bhh[bidx] : bih[bidx];
    }
    if (tid < 48) {
        int k = tid / 16, o = tid % 16;
        wsm[tid] = Wsel[(size_t)k * WS_ + blockIdx.y * 16 + o];
    }
    __syncthreads();

    // gates: thread = (row, o-half); 8 o's each
    {
        const int row = tid >> 1;
        const int half = tid & 1;
        const int t_g = t0 + row;
        const int o0 = half * 8;
        float aD[9];
#pragma unroll
        for (int v = 0; v < 9; v++) aD[v] = 0.f;
        __half hbuf[3][8];

#pragma unroll
        for (int oo = 0; oo < 8; oo++) {
            int o = o0 + oo;
            const float* vr = e + row * ESTRIDE + o * 9;
            const float* bb = bsm + o * 18;
#pragma unroll
            for (int j = 0; j < 3; j++) {
                float ir  = vr[j * 3 + 0] + bb[j * 6 + 0] + bb[j * 6 + 1];
                float iz  = vr[j * 3 + 1] + bb[j * 6 + 2] + bb[j * 6 + 3];
                float inn = vr[j * 3 + 2] + bb[j * 6 + 4];
                float hn  = bb[j * 6 + 5];
                float r = fsig(ir);
                float z = fsig(iz);
                float h = (1.0f - z) * ftanh(inn + r * hn);
                hbuf[j][oo] = __float2half_rn(h);
                aD[j * 3 + 0] = fmaf(h, wsm[0 * 16 + o], aD[j * 3 + 0]);
                aD[j * 3 + 1] = fmaf(h, wsm[1 * 16 + o], aD[j * 3 + 1]);
                aD[j * 3 + 2] = fmaf(h, wsm[2 * 16 + o], aD[j * 3 + 2]);
            }
        }
        // Hall writes (8 halves = 16B per j)
        int og0 = blockIdx.y * 16 + o0;
#pragma unroll
        for (int j = 0; j < 3; j++)
            *(uint4*)&g_Hall[((size_t)t_g * K_ + j) * HD + og0] = *(uint4*)hbuf[j];
        // pair-combine (row-mate is adjacent lane), then atomics from even tid
#pragma unroll
        for (int v = 0; v < 9; v++)
            aD[v] += __shfl_xor_sync(0xffffffffu, aD[v], 1);
        if (half == 0) {
#pragma unroll
            for (int v = 0; v < 9; v++)
                atomicAdd(&g_D[(size_t)t_g * 9 + v], aD[v]);
        }
    }
}

// ---------------------------------------------------------------------------
// K_SELX: sel_x[t][k] = x[t] . Wsel[k][H:] + bsel[k]
// ---------------------------------------------------------------------------
__global__ __launch_bounds__(256) void k_selx(
    const float* __restrict__ xs, const float* __restrict__ Wsel,
    const float* __restrict__ bsel)
{
    const int t = blockIdx.x;
    const int tid = threadIdx.x;
    const float* xrow = xs + (size_t)t * I_;
    float aS[3] = {0.f, 0.f, 0.f};
    for (int i4 = tid; i4 < I_ / 4; i4 += 256) {
        const int i = i4 * 4;
        float4 xv = *(const float4*)&xrow[i];
        float4 u0 = *(const float4*)&Wsel[0 * WS_ + HD + i];
        float4 u1 = *(const float4*)&Wsel[1 * WS_ + HD + i];
        float4 u2 = *(const float4*)&Wsel[2 * WS_ + HD + i];
        aS[0] += xv.x * u0.x + xv.y * u0.y + xv.z * u0.z + xv.w * u0.w;
        aS[1] += xv.x * u1.x + xv.y * u1.y + xv.z * u1.z + xv.w * u1.w;
        aS[2] += xv.x * u2.x + xv.y * u2.y + xv.z * u2.z + xv.w * u2.w;
    }
    __shared__ float red[3][8];
    int lane = tid & 31, w = tid >> 5;
#pragma unroll
    for (int v = 0; v < 3; v++) {
        float s = aS[v];
        for (int off = 16; off > 0; off >>= 1)
            s += __shfl_down_sync(0xffffffffu, s, off);
        if (lane == 0) red[v][w] = s;
    }
    __syncthreads();
    if (tid < 3) {
        float s = 0.f;
#pragma unroll
        for (int ww = 0; ww < 8; ww++) s += red[tid][ww];
        g_selx[(size_t)t * 3 + tid] = s + bsel[tid];
    }
}

// ---------------------------------------------------------------------------
__global__ void k_zero() { g_fixn = 0; }

// ---------------------------------------------------------------------------
// K3a: flag ambiguous steps
// ---------------------------------------------------------------------------
__global__ void k3_flag()
{
    int t = blockIdx.x * blockDim.x + threadIdx.x;
    if (t < 1 || t >= T_) return;
    const float* d = g_D + (size_t)(t - 1) * 9;
    float s0 = g_selx[t * 3 + 0];
    float s1 = g_selx[t * 3 + 1];
    float s2 = g_selx[t * 3 + 2];
    bool amb = false;
#pragma unroll
    for (int j = 0; j < 3; j++) {
        float l0 = d[j * 3 + 0] + s0;
        float l1 = d[j * 3 + 1] + s1;
        float l2 = d[j * 3 + 2] + s2;
        float hi1 = fmaxf(l0, fmaxf(l1, l2));
        float lo1 = fminf(l0, fminf(l1, l2));
        float mid = l0 + l1 + l2 - hi1 - lo1;
        if (hi1 - mid < THETA) amb = true;
    }
    if (amb) {
        int idx = atomicAdd(&g_fixn, 1);
        if (idx < MAXF) g_fixlist[idx] = t - 1;
    }
}

// ---------------------------------------------------------------------------
// K3b-fix1: exact gi rows (ORIGINAL layout) for flagged steps
// ---------------------------------------------------------------------------
__global__ __launch_bounds__(256) void k_fixgemm(
    const float* __restrict__ xs, const float* __restrict__ Wih)
{
    int n = g_fixn; if (n > MAXF) n = MAXF;
    const int fbase = blockIdx.y * 32;
    if (fbase >= n) return;
    const int c0 = blockIdx.x * 128;
    const int tid = threadIdx.x;

    __shared__ float ws[32][129];
    __shared__ float xsm[32][33];
    __shared__ int tlist[32];

    if (tid < 32) tlist[tid] = (fbase + tid < n) ? g_fixlist[fbase + tid] : -1;
    __syncthreads();

    const int c_loc = tid & 127;
    const int fgrp = (tid >> 7) * 16;

    float acc[16];
#pragma unroll
    for (int f = 0; f < 16; f++) acc[f] = 0.f;

    for (int kc0 = 0; kc0 < I_; kc0 += 32) {
        __syncthreads();
#pragma unroll
        for (int q = 0; q < 16; q++) {
            int lin = q * 256 + tid;
            int c = lin >> 5, k = lin & 31;
            ws[k][c] = Wih[(size_t)(c0 + c) * I_ + kc0 + k];
        }
#pragma unroll
        for (int q = 0; q < 4; q++) {
            int lin = q * 256 + tid;
            int f = lin >> 5, k = lin & 31;
            int t1 = tlist[f];
            xsm[f][k] = (t1 >= 0) ? xs[(size_t)t1 * I_ + kc0 + k] : 0.f;
        }
        __syncthreads();

#pragma unroll 4
        for (int k = 0; k < 32; k++) {
            float w = ws[k][c_loc];
#pragma unroll
            for (int f = 0; f < 16; f++)
                acc[f] = fmaf(xsm[fgrp + f][k], w, acc[f]);
        }
    }

#pragma unroll
    for (int f = 0; f < 16; f++) {
        int fg = fbase + fgrp + f;
        if (fg < n) g_dfix[(size_t)fg * NCOL + c0 + c_loc] = acc[f];
    }
}

// ---------------------------------------------------------------------------
// K3b-fix2: exact D rows for flagged steps (overwrites atomic sums).
// ---------------------------------------------------------------------------
__global__ __launch_bounds__(256) void k_fixD(
    const float* __restrict__ Wsel,
    const float* __restrict__ bih, const float* __restrict__ bhh)
{
    int n = g_fixn; if (n > MAXF) n = MAXF;
    const int fi = blockIdx.x;
    if (fi >= n) return;
    const int t1 = g_fixlist[fi];
    const int j = blockIdx.y;
    const int tid = threadIdx.x;

    const size_t db = (size_t)fi * NCOL + (size_t)j * 3 * HD;
    const float* bi = bih + (size_t)j * 3 * HD;
    const float* bh = bhh + (size_t)j * 3 * HD;

    float p0 = 0.f, p1 = 0.f, p2 = 0.f;
    for (int o = tid; o < HD; o += 256) {
        float ir  = g_dfix[db + o]          + bi[o]          + bh[o];
        float iz  = g_dfix[db + HD + o]     + bi[HD + o]     + bh[HD + o];
        float inn = g_dfix[db + 2 * HD + o] + bi[2 * HD + o];
        float hn  = bh[2 * HD + o];
        float r = 1.0f / (1.0f + expf(-ir));
        float z = 1.0f / (1.0f + expf(-iz));
        float nn = tanhf(inn + r * hn);
        float h = (1.0f - z) * nn;
        p0 = fmaf(Wsel[0 * WS_ + o], h, p0);
        p1 = fmaf(Wsel[1 * WS_ + o], h, p1);
        p2 = fmaf(Wsel[2 * WS_ + o], h, p2);
    }

    __shared__ float red[3][8];
    int lane = tid & 31, w = tid >> 5;
    float v[3] = {p0, p1, p2};
#pragma unroll
    for (int q = 0; q < 3; q++) {
        float s = v[q];
        for (int off = 16; off > 0; off >>= 1)
            s += __shfl_down_sync(0xffffffffu, s, off);
        if (lane == 0) red[q][w] = s;
    }
    __syncthreads();
    if (tid < 3) {
        float s = 0.f;
#pragma unroll
        for (int ww = 0; ww < 8; ww++) s += red[tid][ww];
        g_D[(size_t)t1 * 9 + j * 3 + tid] = s;
    }
}

// ---------------------------------------------------------------------------
// K3: packed transition maps
// ---------------------------------------------------------------------------
__global__ void k3_f()
{
    int t = blockIdx.x * blockDim.x + threadIdx.x;
    if (t < 1 || t >= T_) return;
    const float* d = g_D + (size_t)(t - 1) * 9;
    float s0 = g_selx[t * 3 + 0];
    float s1 = g_selx[t * 3 + 1];
    float s2 = g_selx[t * 3 + 2];
    unsigned int word = 0;
#pragma unroll
    for (int j = 0; j < 3; j++) {
        float l0 = d[j * 3 + 0] + s0;
        float l1 = d[j * 3 + 1] + s1;
        float l2 = d[j * 3 + 2] + s2;
        int best = 0; float bv = l0;
        if (l1 > bv) { bv = l1; best = 1; }
        if (l2 > bv) { best = 2; }
        word |= (unsigned int)best << (8 * j);
    }
    g_fw[t] = word;
}

// ---------------------------------------------------------------------------
// K4: function-composition scan
// ---------------------------------------------------------------------------
__global__ __launch_bounds__(1024) void k4_scan()
{
    __shared__ unsigned int comp[1024];
    const int tid = threadIdx.x;

    uint4 raw = *(const uint4*)&g_fw[tid * 4];
    unsigned int m0 = (tid == 0) ? IDMAP : raw.x;
    unsigned int m1 = raw.y, m2 = raw.z, m3 = raw.w;

    unsigned int c0 = m0;
    unsigned int c1 = mcompose(m1, c0);
    unsigned int c2 = mcompose(m2, c1);
    unsigned int c3 = mcompose(m3, c2);

    comp[tid] = c3;
    __syncthreads();

    for (int off = 1; off < 1024; off <<= 1) {
        unsigned int self = comp[tid];
        unsigned int u = (tid >= off) ? comp[tid - off] : IDMAP;
        __syncthreads();
        comp[tid] = mcompose(self, u);
        __syncthreads();
    }

    unsigned int P = (tid == 0) ? IDMAP : comp[tid - 1];
    unsigned int s0 = P & 3u;

    int4 o;
    o.x = (int)((c0 >> (8 * s0)) & 3u);
    o.y = (int)((c1 >> (8 * s0)) & 3u);
    o.z = (int)((c2 >> (8 * s0)) & 3u);
    o.w = (int)((c3 >> (8 * s0)) & 3u);
    *(int4*)&g_kk[tid * 4] = o;
}

// ---------------------------------------------------------------------------
// K5: gather (fp16 Hall -> fp32 out)
// ---------------------------------------------------------------------------
__global__ __launch_bounds__(256) void k5_gather(float* __restrict__ out)
{
    int t = blockIdx.x;
    int tt = (t == T_) ? (T_ - 1) : t;
    int sel = g_kk[tt];
    const __half* src = g_Hall + ((size_t)tt * K_ + sel) * HD;
    float* dst = out + (size_t)t * HD;
    for (int i = threadIdx.x; i < HD / 4; i += 256) {
        uint2 raw = *(const uint2*)&src[i * 4];
        float2 a = __half22float2(*(const __half2*)&raw.x);
        float2 b = __half22float2(*(const __half2*)&raw.y);
        float4 o = make_float4(a.x, a.y, b.x, b.y);
        *(float4*)&dst[i * 4] = o;
    }
}

// ---------------------------------------------------------------------------
extern "C" void kernel_launch(void* const* d_in, const int* in_sizes, int n_in,
                              void* d_out, int out_size)
{
    const float* x    = (const float*)d_in[0];
    const float* Wih  = (const float*)d_in[1];
    // d_in[2] = W_hh : unused (only b_hh enters the math)
    const float* bih  = (const float*)d_in[3];
    const float* bhh  = (const float*)d_in[4];
    const float* Wsel = (const float*)d_in[5];
    const float* bsel = (const float*)d_in[6];
    float* out = (float*)d_out;

    __half *xhi, *whi;
    cudaGetSymbolAddress((void**)&xhi, g_xhi);
    cudaGetSymbolAddress((void**)&whi, g_whi);

    cudaFuncSetAttribute(k1_mma, cudaFuncAttributeMaxDynamicSharedMemorySize, K1_SMEM);

    size_t nx4 = (size_t)T_ * I_ / 4;
    size_t nw4 = (size_t)NCOL * I_ / 4;
    k0_half<<<(int)((nx4 + 255) / 256), 256>>>(x, xhi, nx4);
    k0_wperm<<<(int)((nw4 + 255) / 256), 256>>>(Wih, whi);
    k_zeroD<<<(T_ * 9 + 255) / 256, 256>>>();

    dim3 g1(T_ / 128, NCOL / 144);   // (32, 128), M-fast
    k1_mma<<<g1, 256, K1_SMEM>>>(xhi, whi, Wsel, bih, bhh);

    k_selx<<<T_, 256>>>(x, Wsel, bsel);

    k_zero<<<1, 1>>>();
    k3_flag<<<(T_ + 255) / 256, 256>>>();
    {
        dim3 gf(NCOL / 128, MAXF / 32);
        k_fixgemm<<<gf, 256>>>(x, Wih);
    }
    {
        dim3 gd(MAXF, 3);
        k_fixD<<<gd, 256>>>(Wsel, bih, bhh);
    }
    k3_f<<<(T_ + 255) / 256, 256>>>();
    k4_scan<<<1, 1024>>>();
    k5_gather<<<T_ + 1, 256>>>(out);
}